// round 2
// baseline (speedup 1.0000x reference)
#include <cuda_runtime.h>
#include <math.h>

#define RADIUS_F 1.3f
#define STEPSZ   0.02f
#define NINT     128

// shared layout (floats): x-row pitch 33, h-row pitch 129, comp 4/thread
#define XPITCH 33
#define HPITCH 129
#define SMEM_FLOATS (128*XPITCH + 128*HPITCH + 128*4)

__global__ __launch_bounds__(128, 2)
void nerf_fused_kernel(
    const float* __restrict__ rays_o,
    const float* __restrict__ rays_d,
    const float* __restrict__ G1,   // (3,256,256,256)
    const float* __restrict__ F,    // (32,16,16,16)
    const float* __restrict__ W0,   // (32,128)
    const float* __restrict__ W1,   // (128,128)
    const float* __restrict__ W2,   // (128,16)
    const float* __restrict__ Wc0,  // (31,64)
    const float* __restrict__ Wc1,  // (64,64)
    const float* __restrict__ Wc2,  // (64,3)
    float* __restrict__ outp)       // (B,3)
{
    extern __shared__ float smem[];
    float* sh_x = smem;                         // [128][33]
    float* sh_h = smem + 128*XPITCH;            // [128][129]
    float* sh_c = smem + 128*XPITCH + 128*HPITCH; // [128][4] alpha,r,g,b

    const int ray = blockIdx.x;
    const int tid = threadIdx.x;

    const float ox = rays_o[ray*3+0], oy = rays_o[ray*3+1], oz = rays_o[ray*3+2];
    float dx = rays_d[ray*3+0], dy = rays_d[ray*3+1], dz = rays_d[ray*3+2];
    const float dn = sqrtf(dx*dx + dy*dy + dz*dz);
    dx /= dn; dy /= dn; dz /= dn;

    const float b  = ox*dx + oy*dy + oz*dz;
    const float cc = ox*ox + oy*oy + oz*oz - RADIUS_F*RADIUS_F;
    const float disc = b*b - cc;
    const bool hit = disc > 0.0f;
    const float s = sqrtf(hit ? disc : 1.0f);
    const float tmin = hit ? fmaxf(-b - s, 0.0f) : 0.0f;
    const float tmax = hit ? (-b + s) : 0.0f;

    const float ti   = tmin + (float)tid * STEPSZ;
    const float ti1  = tmin + (float)(tid+1) * STEPSZ;
    const float tmid = 0.5f*(ti + ti1);
    const bool mask = hit && (tmid <= tmax);

    float alpha = 0.0f, crr = 0.0f, cgg = 0.0f, cbb = 0.0f;

    if (mask) {
        // ---- world point -> [-1,1] coords
        const float px = (ox + dx*tmid) / RADIUS_F;
        const float py = (oy + dy*tmid) / RADIUS_F;
        const float pz = (oz + dz*tmid) / RADIUS_F;

        // ---- trilinear sample G1 (3 channels, 256^3)
        float gi[3];
        {
            float fx = fminf(fmaxf((px + 1.0f)*0.5f*255.0f, 0.0f), 255.0f);
            float fy = fminf(fmaxf((py + 1.0f)*0.5f*255.0f, 0.0f), 255.0f);
            float fz = fminf(fmaxf((pz + 1.0f)*0.5f*255.0f, 0.0f), 255.0f);
            int x0 = (int)floorf(fx), y0 = (int)floorf(fy), z0 = (int)floorf(fz);
            int x1 = min(x0+1, 255), y1 = min(y0+1, 255), z1 = min(z0+1, 255);
            float wx = fx - (float)x0, wy = fy - (float)y0, wz = fz - (float)z0;
            int o00 = z0*65536 + y0*256;
            int o01 = z0*65536 + y1*256;
            int o10 = z1*65536 + y0*256;
            int o11 = z1*65536 + y1*256;
            #pragma unroll
            for (int ch = 0; ch < 3; ch++) {
                const float* g = G1 + ch*16777216;
                float v000 = __ldg(g + o00 + x0), v001 = __ldg(g + o00 + x1);
                float v010 = __ldg(g + o01 + x0), v011 = __ldg(g + o01 + x1);
                float v100 = __ldg(g + o10 + x0), v101 = __ldg(g + o10 + x1);
                float v110 = __ldg(g + o11 + x0), v111 = __ldg(g + o11 + x1);
                float c00 = v000*(1.0f-wx) + v001*wx;
                float c01 = v010*(1.0f-wx) + v011*wx;
                float c10 = v100*(1.0f-wx) + v101*wx;
                float c11 = v110*(1.0f-wx) + v111*wx;
                float c0  = c00*(1.0f-wy) + c01*wy;
                float c1  = c10*(1.0f-wy) + c11*wy;
                gi[ch] = c0*(1.0f-wz) + c1*wz;
            }
        }

        // ---- trilinear sample F (32 channels, 16^3), coords = gi
        float* xr = sh_x + tid*XPITCH;
        {
            float fx = fminf(fmaxf((gi[0] + 1.0f)*7.5f, 0.0f), 15.0f);
            float fy = fminf(fmaxf((gi[1] + 1.0f)*7.5f, 0.0f), 15.0f);
            float fz = fminf(fmaxf((gi[2] + 1.0f)*7.5f, 0.0f), 15.0f);
            int x0 = (int)floorf(fx), y0 = (int)floorf(fy), z0 = (int)floorf(fz);
            int x1 = min(x0+1, 15), y1 = min(y0+1, 15), z1 = min(z0+1, 15);
            float wx = fx - (float)x0, wy = fy - (float)y0, wz = fz - (float)z0;
            float mx = 1.0f - wx, my = 1.0f - wy, mz = 1.0f - wz;
            float w000 = mx*my*mz, w001 = wx*my*mz;
            float w010 = mx*wy*mz, w011 = wx*wy*mz;
            float w100 = mx*my*wz, w101 = wx*my*wz;
            float w110 = mx*wy*wz, w111 = wx*wy*wz;
            int b000 = z0*256 + y0*16 + x0;
            int b001 = z0*256 + y0*16 + x1;
            int b010 = z0*256 + y1*16 + x0;
            int b011 = z0*256 + y1*16 + x1;
            int b100 = z1*256 + y0*16 + x0;
            int b101 = z1*256 + y0*16 + x1;
            int b110 = z1*256 + y1*16 + x0;
            int b111 = z1*256 + y1*16 + x1;
            #pragma unroll 4
            for (int ch = 0; ch < 32; ch++) {
                const float* f = F + ch*4096;
                float v = __ldg(f + b000)*w000 + __ldg(f + b001)*w001
                        + __ldg(f + b010)*w010 + __ldg(f + b011)*w011
                        + __ldg(f + b100)*w100 + __ldg(f + b101)*w101
                        + __ldg(f + b110)*w110 + __ldg(f + b111)*w111;
                xr[ch] = v;
            }
        }

        float* hr = sh_h + tid*HPITCH;

        // ---- sigma MLP layer 1: 32 -> 128 (relu), stored to shared
        #pragma unroll
        for (int jt = 0; jt < 4; jt++) {
            float acc[32];
            #pragma unroll
            for (int j = 0; j < 32; j++) acc[j] = 0.0f;
            #pragma unroll 4
            for (int i = 0; i < 32; i++) {
                const float xv = xr[i];
                const float4* w = (const float4*)(W0 + i*128 + jt*32);
                #pragma unroll
                for (int q = 0; q < 8; q++) {
                    float4 ww = __ldg(w + q);
                    acc[q*4+0] = fmaf(xv, ww.x, acc[q*4+0]);
                    acc[q*4+1] = fmaf(xv, ww.y, acc[q*4+1]);
                    acc[q*4+2] = fmaf(xv, ww.z, acc[q*4+2]);
                    acc[q*4+3] = fmaf(xv, ww.w, acc[q*4+3]);
                }
            }
            #pragma unroll
            for (int j = 0; j < 32; j++) hr[jt*32+j] = fmaxf(acc[j], 0.0f);
        }

        // ---- sigma MLP layer 2 (128->128 relu) fused with layer 3 (128->16)
        float so[16];
        #pragma unroll
        for (int k = 0; k < 16; k++) so[k] = 0.0f;
        #pragma unroll
        for (int jt = 0; jt < 4; jt++) {
            float acc[32];
            #pragma unroll
            for (int j = 0; j < 32; j++) acc[j] = 0.0f;
            #pragma unroll 4
            for (int i = 0; i < 128; i++) {
                const float hv = hr[i];
                const float4* w = (const float4*)(W1 + i*128 + jt*32);
                #pragma unroll
                for (int q = 0; q < 8; q++) {
                    float4 ww = __ldg(w + q);
                    acc[q*4+0] = fmaf(hv, ww.x, acc[q*4+0]);
                    acc[q*4+1] = fmaf(hv, ww.y, acc[q*4+1]);
                    acc[q*4+2] = fmaf(hv, ww.z, acc[q*4+2]);
                    acc[q*4+3] = fmaf(hv, ww.w, acc[q*4+3]);
                }
            }
            #pragma unroll
            for (int j = 0; j < 32; j++) {
                const float a = fmaxf(acc[j], 0.0f);
                const float4* w2 = (const float4*)(W2 + (jt*32+j)*16);
                #pragma unroll
                for (int q = 0; q < 4; q++) {
                    float4 ww = __ldg(w2 + q);
                    so[q*4+0] = fmaf(a, ww.x, so[q*4+0]);
                    so[q*4+1] = fmaf(a, ww.y, so[q*4+1]);
                    so[q*4+2] = fmaf(a, ww.z, so[q*4+2]);
                    so[q*4+3] = fmaf(a, ww.w, so[q*4+3]);
                }
            }
        }

        // ---- SH encoding + color-MLP input (31) into shared
        {
            const float x = dx, y = dy, z = dz;
            const float xx = x*x, yy = y*y, zz = z*z;
            const float xy = x*y, yz = y*z, xz = x*z;
            xr[0]  = 0.28209479177387814f;
            xr[1]  = -0.48860251190291987f*y;
            xr[2]  =  0.48860251190291987f*z;
            xr[3]  = -0.48860251190291987f*x;
            xr[4]  =  1.0925484305920792f*xy;
            xr[5]  = -1.0925484305920792f*yz;
            xr[6]  =  0.94617469575756f*zz - 0.31539156525252f;
            xr[7]  = -1.0925484305920792f*xz;
            xr[8]  =  0.5462742152960396f*(xx - yy);
            xr[9]  =  0.5900435899266435f*y*(-3.0f*xx + yy);
            xr[10] =  2.890611442640554f*xy*z;
            xr[11] =  0.4570457994644657f*y*(1.0f - 5.0f*zz);
            xr[12] =  0.3731763325901154f*z*(5.0f*zz - 3.0f);
            xr[13] =  0.4570457994644657f*x*(1.0f - 5.0f*zz);
            xr[14] =  1.445305721320277f*z*(xx - yy);
            xr[15] =  0.5900435899266435f*x*(-xx + 3.0f*yy);
            #pragma unroll
            for (int k = 1; k < 16; k++) xr[16 + k - 1] = so[k];
        }

        // ---- color MLP layer 1: 31 -> 64 (relu) into shared
        #pragma unroll
        for (int jt = 0; jt < 2; jt++) {
            float acc[32];
            #pragma unroll
            for (int j = 0; j < 32; j++) acc[j] = 0.0f;
            #pragma unroll 4
            for (int i = 0; i < 31; i++) {
                const float xv = xr[i];
                const float4* w = (const float4*)(Wc0 + i*64 + jt*32);
                #pragma unroll
                for (int q = 0; q < 8; q++) {
                    float4 ww = __ldg(w + q);
                    acc[q*4+0] = fmaf(xv, ww.x, acc[q*4+0]);
                    acc[q*4+1] = fmaf(xv, ww.y, acc[q*4+1]);
                    acc[q*4+2] = fmaf(xv, ww.z, acc[q*4+2]);
                    acc[q*4+3] = fmaf(xv, ww.w, acc[q*4+3]);
                }
            }
            #pragma unroll
            for (int j = 0; j < 32; j++) hr[jt*32+j] = fmaxf(acc[j], 0.0f);
        }

        // ---- color MLP layer 2 (64->64 relu) fused with layer 3 (64->3)
        float col[3] = {0.0f, 0.0f, 0.0f};
        #pragma unroll
        for (int jt = 0; jt < 2; jt++) {
            float acc[32];
            #pragma unroll
            for (int j = 0; j < 32; j++) acc[j] = 0.0f;
            #pragma unroll 4
            for (int i = 0; i < 64; i++) {
                const float hv = hr[i];
                const float4* w = (const float4*)(Wc1 + i*64 + jt*32);
                #pragma unroll
                for (int q = 0; q < 8; q++) {
                    float4 ww = __ldg(w + q);
                    acc[q*4+0] = fmaf(hv, ww.x, acc[q*4+0]);
                    acc[q*4+1] = fmaf(hv, ww.y, acc[q*4+1]);
                    acc[q*4+2] = fmaf(hv, ww.z, acc[q*4+2]);
                    acc[q*4+3] = fmaf(hv, ww.w, acc[q*4+3]);
                }
            }
            #pragma unroll
            for (int j = 0; j < 32; j++) {
                const float a = fmaxf(acc[j], 0.0f);
                const float* w2 = Wc2 + (jt*32+j)*3;
                col[0] = fmaf(a, __ldg(w2 + 0), col[0]);
                col[1] = fmaf(a, __ldg(w2 + 1), col[1]);
                col[2] = fmaf(a, __ldg(w2 + 2), col[2]);
            }
        }

        const float sigma = fmaxf(so[0], 0.0f);
        alpha = 1.0f - expf(-sigma * STEPSZ);
        crr = 1.0f / (1.0f + expf(-col[0]));
        cgg = 1.0f / (1.0f + expf(-col[1]));
        cbb = 1.0f / (1.0f + expf(-col[2]));
    }

    sh_c[tid*4+0] = alpha;
    sh_c[tid*4+1] = crr;
    sh_c[tid*4+2] = cgg;
    sh_c[tid*4+3] = cbb;
    __syncthreads();

    if (tid == 0) {
        float T = 1.0f, wsum = 0.0f;
        float r = 0.0f, g = 0.0f, bl = 0.0f;
        #pragma unroll 4
        for (int i = 0; i < NINT; i++) {
            const float a = sh_c[i*4+0];
            const float w = a * T;
            r   = fmaf(w, sh_c[i*4+1], r);
            g   = fmaf(w, sh_c[i*4+2], g);
            bl  = fmaf(w, sh_c[i*4+3], bl);
            wsum += w;
            T *= (1.0f - a + 1e-10f);
        }
        const float bg = 1.0f - wsum;
        outp[ray*3+0] = r  + bg;
        outp[ray*3+1] = g  + bg;
        outp[ray*3+2] = bl + bg;
    }
}

extern "C" void kernel_launch(void* const* d_in, const int* in_sizes, int n_in,
                              void* d_out, int out_size)
{
    const float* rays_o = (const float*)d_in[0];
    const float* rays_d = (const float*)d_in[1];
    const float* G1     = (const float*)d_in[2];
    const float* F      = (const float*)d_in[3];
    const float* W0     = (const float*)d_in[4];
    const float* W1     = (const float*)d_in[5];
    const float* W2     = (const float*)d_in[6];
    const float* Wc0    = (const float*)d_in[7];
    const float* Wc1    = (const float*)d_in[8];
    const float* Wc2    = (const float*)d_in[9];
    float* outp = (float*)d_out;

    const int B = in_sizes[0] / 3;
    const size_t smem_bytes = SMEM_FLOATS * sizeof(float);
    cudaFuncSetAttribute(nerf_fused_kernel,
                         cudaFuncAttributeMaxDynamicSharedMemorySize,
                         (int)smem_bytes);
    nerf_fused_kernel<<<B, 128, smem_bytes>>>(
        rays_o, rays_d, G1, F, W0, W1, W2, Wc0, Wc1, Wc2, outp);
}

// round 5
// speedup vs baseline: 1.3506x; 1.3506x over previous
#include <cuda_runtime.h>
#include <math.h>

typedef unsigned long long ull;

#define RADIUS_F 1.3f
#define STEPSZ   0.02f
#define HP 129                       // h row pitch (odd -> conflict-free)
#define SMEM_FLOATS (2*64*HP + 128*4)

// F transposed to (idx, 32 ch) so one corner = 8 x LDG.128
__device__ float g_Ft[131072];

__global__ void transpose_F_kernel(const float* __restrict__ F) {
    int e = blockIdx.x * blockDim.x + threadIdx.x;   // 131072 total
    int ch  = e >> 12;
    int idx = e & 4095;
    g_Ft[idx * 32 + ch] = F[e];
}

__device__ __forceinline__ ull pack2(float v) {
    ull r; asm("mov.b64 %0, {%1,%1};" : "=l"(r) : "f"(v)); return r;
}
__device__ __forceinline__ void ffma2(ull& d, ull a, ull b) {
    asm("fma.rn.f32x2 %0, %1, %2, %0;" : "+l"(d) : "l"(a), "l"(b));
}
__device__ __forceinline__ float2 unpack2(ull v) {
    float2 f; asm("mov.b64 {%0,%1}, %2;" : "=f"(f.x), "=f"(f.y) : "l"(v)); return f;
}

// G1 trilinear (3ch, 256^3) then F trilinear (32ch via g_Ft) -> x[32]
__device__ __forceinline__ void sample_feats(const float* __restrict__ G1,
                                             float px, float py, float pz,
                                             float* __restrict__ x)
{
    float gi[3];
    {
        float fx = fminf(fmaxf((px + 1.0f)*0.5f*255.0f, 0.0f), 255.0f);
        float fy = fminf(fmaxf((py + 1.0f)*0.5f*255.0f, 0.0f), 255.0f);
        float fz = fminf(fmaxf((pz + 1.0f)*0.5f*255.0f, 0.0f), 255.0f);
        int x0 = (int)floorf(fx), y0 = (int)floorf(fy), z0 = (int)floorf(fz);
        int x1 = min(x0+1, 255), y1 = min(y0+1, 255), z1 = min(z0+1, 255);
        float wx = fx - (float)x0, wy = fy - (float)y0, wz = fz - (float)z0;
        int o00 = z0*65536 + y0*256;
        int o01 = z0*65536 + y1*256;
        int o10 = z1*65536 + y0*256;
        int o11 = z1*65536 + y1*256;
        #pragma unroll
        for (int ch = 0; ch < 3; ch++) {
            const float* g = G1 + ch*16777216;
            float v000 = __ldg(g + o00 + x0), v001 = __ldg(g + o00 + x1);
            float v010 = __ldg(g + o01 + x0), v011 = __ldg(g + o01 + x1);
            float v100 = __ldg(g + o10 + x0), v101 = __ldg(g + o10 + x1);
            float v110 = __ldg(g + o11 + x0), v111 = __ldg(g + o11 + x1);
            float c00 = v000*(1.0f-wx) + v001*wx;
            float c01 = v010*(1.0f-wx) + v011*wx;
            float c10 = v100*(1.0f-wx) + v101*wx;
            float c11 = v110*(1.0f-wx) + v111*wx;
            float c0  = c00*(1.0f-wy) + c01*wy;
            float c1  = c10*(1.0f-wy) + c11*wy;
            gi[ch] = c0*(1.0f-wz) + c1*wz;
        }
    }
    {
        float fx = fminf(fmaxf((gi[0] + 1.0f)*7.5f, 0.0f), 15.0f);
        float fy = fminf(fmaxf((gi[1] + 1.0f)*7.5f, 0.0f), 15.0f);
        float fz = fminf(fmaxf((gi[2] + 1.0f)*7.5f, 0.0f), 15.0f);
        int x0 = (int)floorf(fx), y0 = (int)floorf(fy), z0 = (int)floorf(fz);
        int x1 = min(x0+1, 15), y1 = min(y0+1, 15), z1 = min(z0+1, 15);
        float wx = fx - (float)x0, wy = fy - (float)y0, wz = fz - (float)z0;
        float mx = 1.0f - wx, my = 1.0f - wy, mz = 1.0f - wz;
        float w000 = mx*my*mz, w001 = wx*my*mz;
        float w010 = mx*wy*mz, w011 = wx*wy*mz;
        float w100 = mx*my*wz, w101 = wx*my*wz;
        float w110 = mx*wy*wz, w111 = wx*wy*wz;
        const float4* fb = (const float4*)g_Ft;
        int b000 = (z0*256 + y0*16 + x0)*8;
        int b001 = (z0*256 + y0*16 + x1)*8;
        int b010 = (z0*256 + y1*16 + x0)*8;
        int b011 = (z0*256 + y1*16 + x1)*8;
        int b100 = (z1*256 + y0*16 + x0)*8;
        int b101 = (z1*256 + y0*16 + x1)*8;
        int b110 = (z1*256 + y1*16 + x0)*8;
        int b111 = (z1*256 + y1*16 + x1)*8;
        #pragma unroll
        for (int q = 0; q < 8; q++) {
            float4 v = __ldg(fb + b000 + q);
            float ax = v.x*w000, ay = v.y*w000, az = v.z*w000, aw = v.w*w000;
            v = __ldg(fb + b001 + q);
            ax = fmaf(v.x, w001, ax); ay = fmaf(v.y, w001, ay);
            az = fmaf(v.z, w001, az); aw = fmaf(v.w, w001, aw);
            v = __ldg(fb + b010 + q);
            ax = fmaf(v.x, w010, ax); ay = fmaf(v.y, w010, ay);
            az = fmaf(v.z, w010, az); aw = fmaf(v.w, w010, aw);
            v = __ldg(fb + b011 + q);
            ax = fmaf(v.x, w011, ax); ay = fmaf(v.y, w011, ay);
            az = fmaf(v.z, w011, az); aw = fmaf(v.w, w011, aw);
            v = __ldg(fb + b100 + q);
            ax = fmaf(v.x, w100, ax); ay = fmaf(v.y, w100, ay);
            az = fmaf(v.z, w100, az); aw = fmaf(v.w, w100, aw);
            v = __ldg(fb + b101 + q);
            ax = fmaf(v.x, w101, ax); ay = fmaf(v.y, w101, ay);
            az = fmaf(v.z, w101, az); aw = fmaf(v.w, w101, aw);
            v = __ldg(fb + b110 + q);
            ax = fmaf(v.x, w110, ax); ay = fmaf(v.y, w110, ay);
            az = fmaf(v.z, w110, az); aw = fmaf(v.w, w110, aw);
            v = __ldg(fb + b111 + q);
            ax = fmaf(v.x, w111, ax); ay = fmaf(v.y, w111, ay);
            az = fmaf(v.z, w111, az); aw = fmaf(v.w, w111, aw);
            x[4*q+0] = ax; x[4*q+1] = ay; x[4*q+2] = az; x[4*q+3] = aw;
        }
    }
}

__global__ __launch_bounds__(64, 3)
void nerf_fused2(
    const float* __restrict__ rays_o,
    const float* __restrict__ rays_d,
    const float* __restrict__ G1,
    const float* __restrict__ W0,   // (32,128)
    const float* __restrict__ W1,   // (128,128)
    const float* __restrict__ W2,   // (128,16)
    const float* __restrict__ Wc0,  // (31,64)
    const float* __restrict__ Wc1,  // (64,64)
    const float* __restrict__ Wc2,  // (64,3)
    float* __restrict__ outp)
{
    extern __shared__ float smem[];
    float* he  = smem;               // [64][HP] sample 2t
    float* ho  = smem + 64*HP;       // [64][HP] sample 2t+1
    float* cmp = smem + 2*64*HP;     // [128][4]

    const int ray = blockIdx.x;
    const int t   = threadIdx.x;

    const float ox = rays_o[ray*3+0], oy = rays_o[ray*3+1], oz = rays_o[ray*3+2];
    float dx = rays_d[ray*3+0], dy = rays_d[ray*3+1], dz = rays_d[ray*3+2];
    const float dn = sqrtf(dx*dx + dy*dy + dz*dz);
    dx /= dn; dy /= dn; dz /= dn;

    const float b  = ox*dx + oy*dy + oz*dz;
    const float cc = ox*ox + oy*oy + oz*oz - RADIUS_F*RADIUS_F;
    const float disc = b*b - cc;
    const bool hit = disc > 0.0f;
    const float s = sqrtf(hit ? disc : 1.0f);
    const float tmin = hit ? fmaxf(-b - s, 0.0f) : 0.0f;
    const float tmax = hit ? (-b + s) : 0.0f;

    const float tm0 = tmin + ((float)(2*t) + 0.5f) * STEPSZ;
    const float tm1 = tm0 + STEPSZ;
    const bool m0 = hit && (tm0 <= tmax);
    const bool m1 = hit && (tm1 <= tmax);

    float A0 = 0.0f, Rr0 = 0.0f, Gg0 = 0.0f, Bb0 = 0.0f;
    float A1 = 0.0f, Rr1 = 0.0f, Gg1 = 0.0f, Bb1 = 0.0f;

    if (m0) {
        float x0[32], x1[32];
        sample_feats(G1, (ox + dx*tm0)/RADIUS_F, (oy + dy*tm0)/RADIUS_F, (oz + dz*tm0)/RADIUS_F, x0);
        sample_feats(G1, (ox + dx*tm1)/RADIUS_F, (oy + dy*tm1)/RADIUS_F, (oz + dz*tm1)/RADIUS_F, x1);

        float* h0 = he + t*HP;
        float* h1 = ho + t*HP;

        // ---- sigma layer 1: 32 -> 128 relu (both samples), to shared
        for (int jt = 0; jt < 4; jt++) {
            ull acc0[16], acc1[16];
            #pragma unroll
            for (int p = 0; p < 16; p++) { acc0[p] = 0ull; acc1[p] = 0ull; }
            #pragma unroll
            for (int i = 0; i < 32; i++) {
                const ull xa = pack2(x0[i]);
                const ull xb = pack2(x1[i]);
                const ulonglong2* w = (const ulonglong2*)(W0 + i*128 + jt*32);
                #pragma unroll
                for (int q = 0; q < 8; q++) {
                    ulonglong2 ww = __ldg(w + q);
                    ffma2(acc0[2*q],   xa, ww.x); ffma2(acc0[2*q+1], xa, ww.y);
                    ffma2(acc1[2*q],   xb, ww.x); ffma2(acc1[2*q+1], xb, ww.y);
                }
            }
            #pragma unroll
            for (int p = 0; p < 16; p++) {
                float2 f0 = unpack2(acc0[p]), f1 = unpack2(acc1[p]);
                h0[jt*32+2*p]   = fmaxf(f0.x, 0.0f);
                h0[jt*32+2*p+1] = fmaxf(f0.y, 0.0f);
                h1[jt*32+2*p]   = fmaxf(f1.x, 0.0f);
                h1[jt*32+2*p+1] = fmaxf(f1.y, 0.0f);
            }
        }

        // ---- sigma layer 2 (128->128 relu) fused with layer 3 (128->16)
        ull s0[8], s1[8];
        #pragma unroll
        for (int p = 0; p < 8; p++) { s0[p] = 0ull; s1[p] = 0ull; }
        for (int jt = 0; jt < 4; jt++) {
            ull acc0[16], acc1[16];
            #pragma unroll
            for (int p = 0; p < 16; p++) { acc0[p] = 0ull; acc1[p] = 0ull; }
            #pragma unroll 4
            for (int i = 0; i < 128; i++) {
                const ull ha = pack2(h0[i]);
                const ull hb = pack2(h1[i]);
                const ulonglong2* w = (const ulonglong2*)(W1 + i*128 + jt*32);
                #pragma unroll
                for (int q = 0; q < 8; q++) {
                    ulonglong2 ww = __ldg(w + q);
                    ffma2(acc0[2*q],   ha, ww.x); ffma2(acc0[2*q+1], ha, ww.y);
                    ffma2(acc1[2*q],   hb, ww.x); ffma2(acc1[2*q+1], hb, ww.y);
                }
            }
            #pragma unroll
            for (int p = 0; p < 16; p++) {
                float2 f0 = unpack2(acc0[p]), f1 = unpack2(acc1[p]);
                const float a0 = fmaxf(f0.x, 0.0f), bb0 = fmaxf(f0.y, 0.0f);
                const float a1 = fmaxf(f1.x, 0.0f), bb1 = fmaxf(f1.y, 0.0f);
                const ull pa0 = pack2(a0), pa1 = pack2(a1);
                const ull pb0 = pack2(bb0), pb1 = pack2(bb1);
                const ulonglong2* w2a = (const ulonglong2*)(W2 + (jt*32+2*p)*16);
                const ulonglong2* w2b = (const ulonglong2*)(W2 + (jt*32+2*p+1)*16);
                #pragma unroll
                for (int q = 0; q < 4; q++) {
                    ulonglong2 wa = __ldg(w2a + q);
                    ffma2(s0[2*q], pa0, wa.x); ffma2(s0[2*q+1], pa0, wa.y);
                    ffma2(s1[2*q], pa1, wa.x); ffma2(s1[2*q+1], pa1, wa.y);
                    ulonglong2 wb = __ldg(w2b + q);
                    ffma2(s0[2*q], pb0, wb.x); ffma2(s0[2*q+1], pb0, wb.y);
                    ffma2(s1[2*q], pb1, wb.x); ffma2(s1[2*q+1], pb1, wb.y);
                }
            }
        }
        float so0f[16], so1f[16];
        #pragma unroll
        for (int p = 0; p < 8; p++) {
            float2 f0 = unpack2(s0[p]), f1 = unpack2(s1[p]);
            so0f[2*p] = f0.x; so0f[2*p+1] = f0.y;
            so1f[2*p] = f1.x; so1f[2*p+1] = f1.y;
        }

        // ---- SH encoding (per ray, same for both samples)
        float enc[16];
        {
            const float x = dx, y = dy, z = dz;
            const float xx = x*x, yy = y*y, zz = z*z;
            const float xy = x*y, yz = y*z, xz = x*z;
            enc[0]  = 0.28209479177387814f;
            enc[1]  = -0.48860251190291987f*y;
            enc[2]  =  0.48860251190291987f*z;
            enc[3]  = -0.48860251190291987f*x;
            enc[4]  =  1.0925484305920792f*xy;
            enc[5]  = -1.0925484305920792f*yz;
            enc[6]  =  0.94617469575756f*zz - 0.31539156525252f;
            enc[7]  = -1.0925484305920792f*xz;
            enc[8]  =  0.5462742152960396f*(xx - yy);
            enc[9]  =  0.5900435899266435f*y*(-3.0f*xx + yy);
            enc[10] =  2.890611442640554f*xy*z;
            enc[11] =  0.4570457994644657f*y*(1.0f - 5.0f*zz);
            enc[12] =  0.3731763325901154f*z*(5.0f*zz - 3.0f);
            enc[13] =  0.4570457994644657f*x*(1.0f - 5.0f*zz);
            enc[14] =  1.445305721320277f*z*(xx - yy);
            enc[15] =  0.5900435899266435f*x*(-xx + 3.0f*yy);
        }

        // ---- color layer 1: 31 -> 64 relu, into shared (reuse h rows)
        float* c0 = h0;
        float* c1 = h1;
        for (int jt = 0; jt < 2; jt++) {
            ull acc0[16], acc1[16];
            #pragma unroll
            for (int p = 0; p < 16; p++) { acc0[p] = 0ull; acc1[p] = 0ull; }
            #pragma unroll
            for (int i = 0; i < 31; i++) {
                const float v0 = (i < 16) ? enc[i] : so0f[i-15];
                const float v1 = (i < 16) ? enc[i] : so1f[i-15];
                const ull xa = pack2(v0);
                const ull xb = pack2(v1);
                const ulonglong2* w = (const ulonglong2*)(Wc0 + i*64 + jt*32);
                #pragma unroll
                for (int q = 0; q < 8; q++) {
                    ulonglong2 ww = __ldg(w + q);
                    ffma2(acc0[2*q],   xa, ww.x); ffma2(acc0[2*q+1], xa, ww.y);
                    ffma2(acc1[2*q],   xb, ww.x); ffma2(acc1[2*q+1], xb, ww.y);
                }
            }
            #pragma unroll
            for (int p = 0; p < 16; p++) {
                float2 f0 = unpack2(acc0[p]), f1 = unpack2(acc1[p]);
                c0[jt*32+2*p]   = fmaxf(f0.x, 0.0f);
                c0[jt*32+2*p+1] = fmaxf(f0.y, 0.0f);
                c1[jt*32+2*p]   = fmaxf(f1.x, 0.0f);
                c1[jt*32+2*p+1] = fmaxf(f1.y, 0.0f);
            }
        }

        // ---- color layer 2 (64->64 relu) fused with layer 3 (64->3)
        float col0x = 0.f, col0y = 0.f, col0z = 0.f;
        float col1x = 0.f, col1y = 0.f, col1z = 0.f;
        for (int jt = 0; jt < 2; jt++) {
            ull acc0[16], acc1[16];
            #pragma unroll
            for (int p = 0; p < 16; p++) { acc0[p] = 0ull; acc1[p] = 0ull; }
            #pragma unroll 4
            for (int i = 0; i < 64; i++) {
                const ull ha = pack2(c0[i]);
                const ull hb = pack2(c1[i]);
                const ulonglong2* w = (const ulonglong2*)(Wc1 + i*64 + jt*32);
                #pragma unroll
                for (int q = 0; q < 8; q++) {
                    ulonglong2 ww = __ldg(w + q);
                    ffma2(acc0[2*q],   ha, ww.x); ffma2(acc0[2*q+1], ha, ww.y);
                    ffma2(acc1[2*q],   hb, ww.x); ffma2(acc1[2*q+1], hb, ww.y);
                }
            }
            #pragma unroll
            for (int p = 0; p < 16; p++) {
                float2 f0 = unpack2(acc0[p]), f1 = unpack2(acc1[p]);
                const float a0 = fmaxf(f0.x, 0.0f), b0v = fmaxf(f0.y, 0.0f);
                const float a1 = fmaxf(f1.x, 0.0f), b1v = fmaxf(f1.y, 0.0f);
                const float* wra = Wc2 + (jt*32+2*p)*3;
                const float* wrb = Wc2 + (jt*32+2*p+1)*3;
                const float wa0 = __ldg(wra+0), wa1 = __ldg(wra+1), wa2 = __ldg(wra+2);
                const float wb0 = __ldg(wrb+0), wb1 = __ldg(wrb+1), wb2 = __ldg(wrb+2);
                col0x = fmaf(a0, wa0, col0x); col0y = fmaf(a0, wa1, col0y); col0z = fmaf(a0, wa2, col0z);
                col0x = fmaf(b0v, wb0, col0x); col0y = fmaf(b0v, wb1, col0y); col0z = fmaf(b0v, wb2, col0z);
                col1x = fmaf(a1, wa0, col1x); col1y = fmaf(a1, wa1, col1y); col1z = fmaf(a1, wa2, col1z);
                col1x = fmaf(b1v, wb0, col1x); col1y = fmaf(b1v, wb1, col1y); col1z = fmaf(b1v, wb2, col1z);
            }
        }

        const float sg0 = fmaxf(so0f[0], 0.0f);
        A0  = 1.0f - expf(-sg0 * STEPSZ);
        Rr0 = 1.0f / (1.0f + expf(-col0x));
        Gg0 = 1.0f / (1.0f + expf(-col0y));
        Bb0 = 1.0f / (1.0f + expf(-col0z));
        if (m1) {
            const float sg1 = fmaxf(so1f[0], 0.0f);
            A1  = 1.0f - expf(-sg1 * STEPSZ);
            Rr1 = 1.0f / (1.0f + expf(-col1x));
            Gg1 = 1.0f / (1.0f + expf(-col1y));
            Bb1 = 1.0f / (1.0f + expf(-col1z));
        }
    }

    cmp[(2*t)*4+0] = A0;  cmp[(2*t)*4+1] = Rr0;
    cmp[(2*t)*4+2] = Gg0; cmp[(2*t)*4+3] = Bb0;
    cmp[(2*t+1)*4+0] = A1;  cmp[(2*t+1)*4+1] = Rr1;
    cmp[(2*t+1)*4+2] = Gg1; cmp[(2*t+1)*4+3] = Bb1;
    __syncthreads();

    if (t == 0) {
        float T = 1.0f, wsum = 0.0f;
        float r = 0.0f, g = 0.0f, bl = 0.0f;
        #pragma unroll 4
        for (int i = 0; i < 128; i++) {
            const float a = cmp[i*4+0];
            const float w = a * T;
            r    = fmaf(w, cmp[i*4+1], r);
            g    = fmaf(w, cmp[i*4+2], g);
            bl   = fmaf(w, cmp[i*4+3], bl);
            wsum += w;
            T *= (1.0f - a + 1e-10f);
        }
        const float bg = 1.0f - wsum;
        outp[ray*3+0] = r  + bg;
        outp[ray*3+1] = g  + bg;
        outp[ray*3+2] = bl + bg;
    }
}

extern "C" void kernel_launch(void* const* d_in, const int* in_sizes, int n_in,
                              void* d_out, int out_size)
{
    const float* rays_o = (const float*)d_in[0];
    const float* rays_d = (const float*)d_in[1];
    const float* G1     = (const float*)d_in[2];
    const float* F      = (const float*)d_in[3];
    const float* W0     = (const float*)d_in[4];
    const float* W1     = (const float*)d_in[5];
    const float* W2     = (const float*)d_in[6];
    const float* Wc0    = (const float*)d_in[7];
    const float* Wc1    = (const float*)d_in[8];
    const float* Wc2    = (const float*)d_in[9];
    float* outp = (float*)d_out;

    const int B = in_sizes[0] / 3;

    transpose_F_kernel<<<512, 256>>>(F);

    const size_t smem_bytes = SMEM_FLOATS * sizeof(float);
    cudaFuncSetAttribute(nerf_fused2,
                         cudaFuncAttributeMaxDynamicSharedMemorySize,
                         (int)smem_bytes);
    nerf_fused2<<<B, 64, smem_bytes>>>(
        rays_o, rays_d, G1, W0, W1, W2, Wc0, Wc1, Wc2, outp);
}

// round 6
// speedup vs baseline: 1.3919x; 1.0306x over previous
#include <cuda_runtime.h>
#include <cuda_bf16.h>
#include <math.h>

typedef unsigned long long ull;

#define RADIUS_F 1.3f
#define STEPSZ   0.02f
#define HP 129   // bf162 row pitch (odd -> conflict-free, 4B elements)
// smem: 64 rows * HP bfloat162 (4B) + 128*4 floats for compositing
#define SMEM_BYTES (64*HP*4 + 128*4*4)

// F transposed to (idx, 32 ch) so one corner = 8 x LDG.128
__device__ float g_Ft[131072];

__global__ void transpose_F_kernel(const float* __restrict__ F) {
    int e = blockIdx.x * blockDim.x + threadIdx.x;   // 131072 total
    int ch  = e >> 12;
    int idx = e & 4095;
    g_Ft[idx * 32 + ch] = F[e];
}

__device__ __forceinline__ ull pack2(float v) {
    ull r; asm("mov.b64 %0, {%1,%1};" : "=l"(r) : "f"(v)); return r;
}
__device__ __forceinline__ void ffma2(ull& d, ull a, ull b) {
    asm("fma.rn.f32x2 %0, %1, %2, %0;" : "+l"(d) : "l"(a), "l"(b));
}
__device__ __forceinline__ float2 unpack2(ull v) {
    float2 f; asm("mov.b64 {%0,%1}, %2;" : "=f"(f.x), "=f"(f.y) : "l"(v)); return f;
}

// G1 trilinear (3ch, 256^3) then F trilinear (32ch via g_Ft) -> x[32] (f32)
__device__ __forceinline__ void sample_feats(const float* __restrict__ G1,
                                             float px, float py, float pz,
                                             float* __restrict__ x)
{
    float gi[3];
    {
        float fx = fminf(fmaxf((px + 1.0f)*0.5f*255.0f, 0.0f), 255.0f);
        float fy = fminf(fmaxf((py + 1.0f)*0.5f*255.0f, 0.0f), 255.0f);
        float fz = fminf(fmaxf((pz + 1.0f)*0.5f*255.0f, 0.0f), 255.0f);
        int x0 = (int)floorf(fx), y0 = (int)floorf(fy), z0 = (int)floorf(fz);
        int x1 = min(x0+1, 255), y1 = min(y0+1, 255), z1 = min(z0+1, 255);
        float wx = fx - (float)x0, wy = fy - (float)y0, wz = fz - (float)z0;
        int o00 = z0*65536 + y0*256;
        int o01 = z0*65536 + y1*256;
        int o10 = z1*65536 + y0*256;
        int o11 = z1*65536 + y1*256;
        #pragma unroll
        for (int ch = 0; ch < 3; ch++) {
            const float* g = G1 + ch*16777216;
            float v000 = __ldg(g + o00 + x0), v001 = __ldg(g + o00 + x1);
            float v010 = __ldg(g + o01 + x0), v011 = __ldg(g + o01 + x1);
            float v100 = __ldg(g + o10 + x0), v101 = __ldg(g + o10 + x1);
            float v110 = __ldg(g + o11 + x0), v111 = __ldg(g + o11 + x1);
            float c00 = v000*(1.0f-wx) + v001*wx;
            float c01 = v010*(1.0f-wx) + v011*wx;
            float c10 = v100*(1.0f-wx) + v101*wx;
            float c11 = v110*(1.0f-wx) + v111*wx;
            float c0  = c00*(1.0f-wy) + c01*wy;
            float c1  = c10*(1.0f-wy) + c11*wy;
            gi[ch] = c0*(1.0f-wz) + c1*wz;
        }
    }
    {
        float fx = fminf(fmaxf((gi[0] + 1.0f)*7.5f, 0.0f), 15.0f);
        float fy = fminf(fmaxf((gi[1] + 1.0f)*7.5f, 0.0f), 15.0f);
        float fz = fminf(fmaxf((gi[2] + 1.0f)*7.5f, 0.0f), 15.0f);
        int x0 = (int)floorf(fx), y0 = (int)floorf(fy), z0 = (int)floorf(fz);
        int x1 = min(x0+1, 15), y1 = min(y0+1, 15), z1 = min(z0+1, 15);
        float wx = fx - (float)x0, wy = fy - (float)y0, wz = fz - (float)z0;
        float mx = 1.0f - wx, my = 1.0f - wy, mz = 1.0f - wz;
        float w000 = mx*my*mz, w001 = wx*my*mz;
        float w010 = mx*wy*mz, w011 = wx*wy*mz;
        float w100 = mx*my*wz, w101 = wx*my*wz;
        float w110 = mx*wy*wz, w111 = wx*wy*wz;
        const float4* fb = (const float4*)g_Ft;
        int b000 = (z0*256 + y0*16 + x0)*8;
        int b001 = (z0*256 + y0*16 + x1)*8;
        int b010 = (z0*256 + y1*16 + x0)*8;
        int b011 = (z0*256 + y1*16 + x1)*8;
        int b100 = (z1*256 + y0*16 + x0)*8;
        int b101 = (z1*256 + y0*16 + x1)*8;
        int b110 = (z1*256 + y1*16 + x0)*8;
        int b111 = (z1*256 + y1*16 + x1)*8;
        #pragma unroll
        for (int q = 0; q < 8; q++) {
            float4 v = __ldg(fb + b000 + q);
            float ax = v.x*w000, ay = v.y*w000, az = v.z*w000, aw = v.w*w000;
            v = __ldg(fb + b001 + q);
            ax = fmaf(v.x, w001, ax); ay = fmaf(v.y, w001, ay);
            az = fmaf(v.z, w001, az); aw = fmaf(v.w, w001, aw);
            v = __ldg(fb + b010 + q);
            ax = fmaf(v.x, w010, ax); ay = fmaf(v.y, w010, ay);
            az = fmaf(v.z, w010, az); aw = fmaf(v.w, w010, aw);
            v = __ldg(fb + b011 + q);
            ax = fmaf(v.x, w011, ax); ay = fmaf(v.y, w011, ay);
            az = fmaf(v.z, w011, az); aw = fmaf(v.w, w011, aw);
            v = __ldg(fb + b100 + q);
            ax = fmaf(v.x, w100, ax); ay = fmaf(v.y, w100, ay);
            az = fmaf(v.z, w100, az); aw = fmaf(v.w, w100, aw);
            v = __ldg(fb + b101 + q);
            ax = fmaf(v.x, w101, ax); ay = fmaf(v.y, w101, ay);
            az = fmaf(v.z, w101, az); aw = fmaf(v.w, w101, aw);
            v = __ldg(fb + b110 + q);
            ax = fmaf(v.x, w110, ax); ay = fmaf(v.y, w110, ay);
            az = fmaf(v.z, w110, az); aw = fmaf(v.w, w110, aw);
            v = __ldg(fb + b111 + q);
            ax = fmaf(v.x, w111, ax); ay = fmaf(v.y, w111, ay);
            az = fmaf(v.z, w111, az); aw = fmaf(v.w, w111, aw);
            x[4*q+0] = ax; x[4*q+1] = ay; x[4*q+2] = az; x[4*q+3] = aw;
        }
    }
}

__global__ __launch_bounds__(64, 6)
void nerf_fused3(
    const float* __restrict__ rays_o,
    const float* __restrict__ rays_d,
    const float* __restrict__ G1,
    const float* __restrict__ W0,   // (32,128)
    const float* __restrict__ W1,   // (128,128)
    const float* __restrict__ W2,   // (128,16)
    const float* __restrict__ Wc0,  // (31,64)
    const float* __restrict__ Wc1,  // (64,64)
    const float* __restrict__ Wc2,  // (64,3)
    float* __restrict__ outp)
{
    extern __shared__ char smemraw[];
    __nv_bfloat162* sh_h = (__nv_bfloat162*)smemraw;          // [64][HP] (h0,h1) pairs
    float* cmp = (float*)(smemraw + 64*HP*4);                 // [128][4]

    const int ray = blockIdx.x;
    const int t   = threadIdx.x;

    const float ox = rays_o[ray*3+0], oy = rays_o[ray*3+1], oz = rays_o[ray*3+2];
    float dx = rays_d[ray*3+0], dy = rays_d[ray*3+1], dz = rays_d[ray*3+2];
    const float dn = sqrtf(dx*dx + dy*dy + dz*dz);
    dx /= dn; dy /= dn; dz /= dn;

    const float b  = ox*dx + oy*dy + oz*dz;
    const float cc = ox*ox + oy*oy + oz*oz - RADIUS_F*RADIUS_F;
    const float disc = b*b - cc;
    const bool hit = disc > 0.0f;
    const float s = sqrtf(hit ? disc : 1.0f);
    const float tmin = hit ? fmaxf(-b - s, 0.0f) : 0.0f;
    const float tmax = hit ? (-b + s) : 0.0f;

    const float tm0 = tmin + ((float)(2*t) + 0.5f) * STEPSZ;
    const float tm1 = tm0 + STEPSZ;
    const bool m0 = hit && (tm0 <= tmax);
    const bool m1 = hit && (tm1 <= tmax);

    float A0 = 0.0f, Rr0 = 0.0f, Gg0 = 0.0f, Bb0 = 0.0f;
    float A1 = 0.0f, Rr1 = 0.0f, Gg1 = 0.0f, Bb1 = 0.0f;

    if (m0) {
        // ---- features for both samples, packed to bf16 pairs (x0[i],x1[i])
        __nv_bfloat162 xq[32];
        {
            float xt[32];
            sample_feats(G1, (ox + dx*tm0)/RADIUS_F, (oy + dy*tm0)/RADIUS_F,
                         (oz + dz*tm0)/RADIUS_F, xt);
            #pragma unroll
            for (int i = 0; i < 32; i++)
                xq[i] = __floats2bfloat162_rn(xt[i], 0.0f);
            sample_feats(G1, (ox + dx*tm1)/RADIUS_F, (oy + dy*tm1)/RADIUS_F,
                         (oz + dz*tm1)/RADIUS_F, xt);
            #pragma unroll
            for (int i = 0; i < 32; i++)
                xq[i] = __floats2bfloat162_rn(__low2float(xq[i]), xt[i]);
        }

        __nv_bfloat162* hrow = sh_h + t*HP;

        // ---- sigma layer 1: 32 -> 128 relu (both samples), to shared (bf16)
        for (int jt = 0; jt < 4; jt++) {
            ull acc0[16], acc1[16];
            #pragma unroll
            for (int p = 0; p < 16; p++) { acc0[p] = 0ull; acc1[p] = 0ull; }
            #pragma unroll
            for (int i = 0; i < 32; i++) {
                const ull xa = pack2(__low2float(xq[i]));
                const ull xb = pack2(__high2float(xq[i]));
                const ulonglong2* w = (const ulonglong2*)(W0 + i*128 + jt*32);
                #pragma unroll
                for (int q = 0; q < 8; q++) {
                    ulonglong2 ww = __ldg(w + q);
                    ffma2(acc0[2*q],   xa, ww.x); ffma2(acc0[2*q+1], xa, ww.y);
                    ffma2(acc1[2*q],   xb, ww.x); ffma2(acc1[2*q+1], xb, ww.y);
                }
            }
            #pragma unroll
            for (int p = 0; p < 16; p++) {
                float2 f0 = unpack2(acc0[p]), f1 = unpack2(acc1[p]);
                hrow[jt*32+2*p]   = __floats2bfloat162_rn(fmaxf(f0.x,0.0f), fmaxf(f1.x,0.0f));
                hrow[jt*32+2*p+1] = __floats2bfloat162_rn(fmaxf(f0.y,0.0f), fmaxf(f1.y,0.0f));
            }
        }

        // ---- sigma layer 2 (128->128 relu) fused with layer 3 (128->16)
        ull s0[8], s1[8];
        #pragma unroll
        for (int p = 0; p < 8; p++) { s0[p] = 0ull; s1[p] = 0ull; }
        for (int jt = 0; jt < 4; jt++) {
            ull acc0[16], acc1[16];
            #pragma unroll
            for (int p = 0; p < 16; p++) { acc0[p] = 0ull; acc1[p] = 0ull; }
            #pragma unroll 4
            for (int i = 0; i < 128; i++) {
                const __nv_bfloat162 hp = hrow[i];
                const ull ha = pack2(__low2float(hp));
                const ull hb = pack2(__high2float(hp));
                const ulonglong2* w = (const ulonglong2*)(W1 + i*128 + jt*32);
                #pragma unroll
                for (int q = 0; q < 8; q++) {
                    ulonglong2 ww = __ldg(w + q);
                    ffma2(acc0[2*q],   ha, ww.x); ffma2(acc0[2*q+1], ha, ww.y);
                    ffma2(acc1[2*q],   hb, ww.x); ffma2(acc1[2*q+1], hb, ww.y);
                }
            }
            #pragma unroll
            for (int p = 0; p < 16; p++) {
                float2 f0 = unpack2(acc0[p]), f1 = unpack2(acc1[p]);
                const float a0 = fmaxf(f0.x, 0.0f), bb0 = fmaxf(f0.y, 0.0f);
                const float a1 = fmaxf(f1.x, 0.0f), bb1 = fmaxf(f1.y, 0.0f);
                const ull pa0 = pack2(a0), pa1 = pack2(a1);
                const ull pb0 = pack2(bb0), pb1 = pack2(bb1);
                const ulonglong2* w2a = (const ulonglong2*)(W2 + (jt*32+2*p)*16);
                const ulonglong2* w2b = (const ulonglong2*)(W2 + (jt*32+2*p+1)*16);
                #pragma unroll
                for (int q = 0; q < 4; q++) {
                    ulonglong2 wa = __ldg(w2a + q);
                    ffma2(s0[2*q], pa0, wa.x); ffma2(s0[2*q+1], pa0, wa.y);
                    ffma2(s1[2*q], pa1, wa.x); ffma2(s1[2*q+1], pa1, wa.y);
                    ulonglong2 wb = __ldg(w2b + q);
                    ffma2(s0[2*q], pb0, wb.x); ffma2(s0[2*q+1], pb0, wb.y);
                    ffma2(s1[2*q], pb1, wb.x); ffma2(s1[2*q+1], pb1, wb.y);
                }
            }
        }
        float so0f[16], so1f[16];
        #pragma unroll
        for (int p = 0; p < 8; p++) {
            float2 f0 = unpack2(s0[p]), f1 = unpack2(s1[p]);
            so0f[2*p] = f0.x; so0f[2*p+1] = f0.y;
            so1f[2*p] = f1.x; so1f[2*p+1] = f1.y;
        }

        // ---- SH encoding (per ray, same for both samples)
        float enc[16];
        {
            const float x = dx, y = dy, z = dz;
            const float xx = x*x, yy = y*y, zz = z*z;
            const float xy = x*y, yz = y*z, xz = x*z;
            enc[0]  = 0.28209479177387814f;
            enc[1]  = -0.48860251190291987f*y;
            enc[2]  =  0.48860251190291987f*z;
            enc[3]  = -0.48860251190291987f*x;
            enc[4]  =  1.0925484305920792f*xy;
            enc[5]  = -1.0925484305920792f*yz;
            enc[6]  =  0.94617469575756f*zz - 0.31539156525252f;
            enc[7]  = -1.0925484305920792f*xz;
            enc[8]  =  0.5462742152960396f*(xx - yy);
            enc[9]  =  0.5900435899266435f*y*(-3.0f*xx + yy);
            enc[10] =  2.890611442640554f*xy*z;
            enc[11] =  0.4570457994644657f*y*(1.0f - 5.0f*zz);
            enc[12] =  0.3731763325901154f*z*(5.0f*zz - 3.0f);
            enc[13] =  0.4570457994644657f*x*(1.0f - 5.0f*zz);
            enc[14] =  1.445305721320277f*z*(xx - yy);
            enc[15] =  0.5900435899266435f*x*(-xx + 3.0f*yy);
        }

        // ---- color layer 1: 31 -> 64 relu, into shared (reuse h rows, bf16)
        for (int jt = 0; jt < 2; jt++) {
            ull acc0[16], acc1[16];
            #pragma unroll
            for (int p = 0; p < 16; p++) { acc0[p] = 0ull; acc1[p] = 0ull; }
            #pragma unroll
            for (int i = 0; i < 31; i++) {
                const float v0 = (i < 16) ? enc[i] : so0f[i-15];
                const float v1 = (i < 16) ? enc[i] : so1f[i-15];
                const ull xa = pack2(v0);
                const ull xb = pack2(v1);
                const ulonglong2* w = (const ulonglong2*)(Wc0 + i*64 + jt*32);
                #pragma unroll
                for (int q = 0; q < 8; q++) {
                    ulonglong2 ww = __ldg(w + q);
                    ffma2(acc0[2*q],   xa, ww.x); ffma2(acc0[2*q+1], xa, ww.y);
                    ffma2(acc1[2*q],   xb, ww.x); ffma2(acc1[2*q+1], xb, ww.y);
                }
            }
            #pragma unroll
            for (int p = 0; p < 16; p++) {
                float2 f0 = unpack2(acc0[p]), f1 = unpack2(acc1[p]);
                hrow[jt*32+2*p]   = __floats2bfloat162_rn(fmaxf(f0.x,0.0f), fmaxf(f1.x,0.0f));
                hrow[jt*32+2*p+1] = __floats2bfloat162_rn(fmaxf(f0.y,0.0f), fmaxf(f1.y,0.0f));
            }
        }

        // ---- color layer 2 (64->64 relu) fused with layer 3 (64->3)
        float col0x = 0.f, col0y = 0.f, col0z = 0.f;
        float col1x = 0.f, col1y = 0.f, col1z = 0.f;
        for (int jt = 0; jt < 2; jt++) {
            ull acc0[16], acc1[16];
            #pragma unroll
            for (int p = 0; p < 16; p++) { acc0[p] = 0ull; acc1[p] = 0ull; }
            #pragma unroll 4
            for (int i = 0; i < 64; i++) {
                const __nv_bfloat162 hp = hrow[i];
                const ull ha = pack2(__low2float(hp));
                const ull hb = pack2(__high2float(hp));
                const ulonglong2* w = (const ulonglong2*)(Wc1 + i*64 + jt*32);
                #pragma unroll
                for (int q = 0; q < 8; q++) {
                    ulonglong2 ww = __ldg(w + q);
                    ffma2(acc0[2*q],   ha, ww.x); ffma2(acc0[2*q+1], ha, ww.y);
                    ffma2(acc1[2*q],   hb, ww.x); ffma2(acc1[2*q+1], hb, ww.y);
                }
            }
            #pragma unroll
            for (int p = 0; p < 16; p++) {
                float2 f0 = unpack2(acc0[p]), f1 = unpack2(acc1[p]);
                const float a0 = fmaxf(f0.x, 0.0f), b0v = fmaxf(f0.y, 0.0f);
                const float a1 = fmaxf(f1.x, 0.0f), b1v = fmaxf(f1.y, 0.0f);
                const float* wra = Wc2 + (jt*32+2*p)*3;
                const float* wrb = Wc2 + (jt*32+2*p+1)*3;
                const float wa0 = __ldg(wra+0), wa1 = __ldg(wra+1), wa2 = __ldg(wra+2);
                const float wb0 = __ldg(wrb+0), wb1 = __ldg(wrb+1), wb2 = __ldg(wrb+2);
                col0x = fmaf(a0, wa0, col0x); col0y = fmaf(a0, wa1, col0y); col0z = fmaf(a0, wa2, col0z);
                col0x = fmaf(b0v, wb0, col0x); col0y = fmaf(b0v, wb1, col0y); col0z = fmaf(b0v, wb2, col0z);
                col1x = fmaf(a1, wa0, col1x); col1y = fmaf(a1, wa1, col1y); col1z = fmaf(a1, wa2, col1z);
                col1x = fmaf(b1v, wb0, col1x); col1y = fmaf(b1v, wb1, col1y); col1z = fmaf(b1v, wb2, col1z);
            }
        }

        const float sg0 = fmaxf(so0f[0], 0.0f);
        A0  = 1.0f - expf(-sg0 * STEPSZ);
        Rr0 = 1.0f / (1.0f + expf(-col0x));
        Gg0 = 1.0f / (1.0f + expf(-col0y));
        Bb0 = 1.0f / (1.0f + expf(-col0z));
        if (m1) {
            const float sg1 = fmaxf(so1f[0], 0.0f);
            A1  = 1.0f - expf(-sg1 * STEPSZ);
            Rr1 = 1.0f / (1.0f + expf(-col1x));
            Gg1 = 1.0f / (1.0f + expf(-col1y));
            Bb1 = 1.0f / (1.0f + expf(-col1z));
        }
    }

    cmp[(2*t)*4+0] = A0;  cmp[(2*t)*4+1] = Rr0;
    cmp[(2*t)*4+2] = Gg0; cmp[(2*t)*4+3] = Bb0;
    cmp[(2*t+1)*4+0] = A1;  cmp[(2*t+1)*4+1] = Rr1;
    cmp[(2*t+1)*4+2] = Gg1; cmp[(2*t+1)*4+3] = Bb1;
    __syncthreads();

    if (t == 0) {
        float T = 1.0f, wsum = 0.0f;
        float r = 0.0f, g = 0.0f, bl = 0.0f;
        #pragma unroll 4
        for (int i = 0; i < 128; i++) {
            const float a = cmp[i*4+0];
            const float w = a * T;
            r    = fmaf(w, cmp[i*4+1], r);
            g    = fmaf(w, cmp[i*4+2], g);
            bl   = fmaf(w, cmp[i*4+3], bl);
            wsum += w;
            T *= (1.0f - a + 1e-10f);
        }
        const float bg = 1.0f - wsum;
        outp[ray*3+0] = r  + bg;
        outp[ray*3+1] = g  + bg;
        outp[ray*3+2] = bl + bg;
    }
}

extern "C" void kernel_launch(void* const* d_in, const int* in_sizes, int n_in,
                              void* d_out, int out_size)
{
    const float* rays_o = (const float*)d_in[0];
    const float* rays_d = (const float*)d_in[1];
    const float* G1     = (const float*)d_in[2];
    const float* F      = (const float*)d_in[3];
    const float* W0     = (const float*)d_in[4];
    const float* W1     = (const float*)d_in[5];
    const float* W2     = (const float*)d_in[6];
    const float* Wc0    = (const float*)d_in[7];
    const float* Wc1    = (const float*)d_in[8];
    const float* Wc2    = (const float*)d_in[9];
    float* outp = (float*)d_out;

    const int B = in_sizes[0] / 3;

    transpose_F_kernel<<<512, 256>>>(F);

    cudaFuncSetAttribute(nerf_fused3,
                         cudaFuncAttributeMaxDynamicSharedMemorySize,
                         SMEM_BYTES);
    nerf_fused3<<<B, 64, SMEM_BYTES>>>(
        rays_o, rays_d, G1, W0, W1, W2, Wc0, Wc1, Wc2, outp);
}

// round 8
// speedup vs baseline: 7.7610x; 5.5757x over previous
#include <cuda_runtime.h>
#include <cuda_bf16.h>
#include <math.h>

typedef unsigned int u32;

#define RADIUS_F 1.3f
#define STEPSZ   0.02f

// ---------------- global scratch (no allocs allowed) ----------------
__device__ float g_Ft[131072];      // F transposed (idx, 32ch)
__device__ u32   g_pack[14592];     // all weights in bf16 B-fragment order

// pack-buffer bases (u32 units)
#define PB_L0 0        // W0  K=32  N=128  KT=2 NT=16 -> 2048
#define PB_L1 2048     // W1  K=128 N=128  KT=8 NT=16 -> 8192
#define PB_L2 10240    // W2  K=128 N=16   KT=8 NT=2  -> 1024 (cols rotated: out col j = orig col j+1, col15 = orig col0 = sigma)
#define PB_C0 11264    // Wc0 K=32(31+pad) N=64 KT=2 NT=8 -> 1024
#define PB_C1 12288    // Wc1 K=64  N=64   KT=4 NT=8 -> 2048
#define PB_C2 14336    // Wc2 K=64  N=8(3+pad) KT=4 NT=1 -> 256

__global__ void transpose_F_kernel(const float* __restrict__ F) {
    int e = blockIdx.x * blockDim.x + threadIdx.x;   // 131072 total
    int ch  = e >> 12;
    int idx = e & 4095;
    g_Ft[idx * 32 + ch] = F[e];
}

// Pack row-major W[K][N] (row stride = rowstride) into mma.sync m16n8k16
// B-fragment order: g_pack[base + ((nt*KT+kt)*32 + lane)*2 + r] =
//   bf16x2{ W[k][n], W[k+1][n] },  k = kt*16 + (lane%4)*2 + r*8, n = nt*8 + lane/4
__global__ void pack_kernel(const float* __restrict__ W, int base, int KT, int NT,
                            int Korig, int Norig, int rowstride, int sig_reorder)
{
    int idx = blockIdx.x * blockDim.x + threadIdx.x;
    int total = NT * KT * 64;
    if (idx >= total) return;
    int r    = idx & 1;
    int lane = (idx >> 1) & 31;
    int t    = idx >> 6;           // = nt*KT + kt
    int kt   = t % KT;
    int nt   = t / KT;
    int k = kt*16 + (lane & 3)*2 + r*8;
    int n = nt*8 + (lane >> 2);
    int nc = sig_reorder ? ((n == 15) ? 0 : n + 1) : n;
    float w0 = (k     < Korig && nc < Norig) ? W[k*rowstride + nc]     : 0.0f;
    float w1 = (k + 1 < Korig && nc < Norig) ? W[(k+1)*rowstride + nc] : 0.0f;
    __nv_bfloat162 p = __floats2bfloat162_rn(w0, w1);   // .x = w0 (low)
    g_pack[base + idx] = *(u32*)&p;
}

// ---------------- device helpers ----------------
__device__ __forceinline__ u32 packbf(float lo, float hi) {
    __nv_bfloat162 p = __floats2bfloat162_rn(lo, hi);
    return *(u32*)&p;
}
__device__ __forceinline__ u32 packbf_relu(float lo, float hi) {
    return packbf(fmaxf(lo, 0.0f), fmaxf(hi, 0.0f));
}
__device__ __forceinline__ void mma_bf16(float* d, const u32* a, const u32* b) {
    asm volatile(
        "mma.sync.aligned.m16n8k16.row.col.f32.bf16.bf16.f32 "
        "{%0,%1,%2,%3},{%4,%5,%6,%7},{%8,%9},{%0,%1,%2,%3};"
        : "+f"(d[0]), "+f"(d[1]), "+f"(d[2]), "+f"(d[3])
        : "r"(a[0]), "r"(a[1]), "r"(a[2]), "r"(a[3]), "r"(b[0]), "r"(b[1]));
}
__device__ __forceinline__ void ldb(u32* b, int base, int nt, int kt, int KT, int lane) {
    const uint2* p = (const uint2*)(g_pack + base + (((nt*KT + kt) << 5) + lane)*2);
    uint2 v = __ldg(p);
    b[0] = v.x; b[1] = v.y;
}
__device__ __forceinline__ float sigm(float v) { return 1.0f / (1.0f + expf(-v)); }

// G1 trilinear (3ch, 256^3) then F trilinear (32ch via g_Ft) -> x[32]
__device__ __forceinline__ void sample_feats(const float* __restrict__ G1,
                                             float px, float py, float pz,
                                             float* __restrict__ x)
{
    float gi[3];
    {
        float fx = fminf(fmaxf((px + 1.0f)*0.5f*255.0f, 0.0f), 255.0f);
        float fy = fminf(fmaxf((py + 1.0f)*0.5f*255.0f, 0.0f), 255.0f);
        float fz = fminf(fmaxf((pz + 1.0f)*0.5f*255.0f, 0.0f), 255.0f);
        int x0 = (int)floorf(fx), y0 = (int)floorf(fy), z0 = (int)floorf(fz);
        int x1 = min(x0+1, 255), y1 = min(y0+1, 255), z1 = min(z0+1, 255);
        float wx = fx - (float)x0, wy = fy - (float)y0, wz = fz - (float)z0;
        int o00 = z0*65536 + y0*256;
        int o01 = z0*65536 + y1*256;
        int o10 = z1*65536 + y0*256;
        int o11 = z1*65536 + y1*256;
        #pragma unroll
        for (int ch = 0; ch < 3; ch++) {
            const float* g = G1 + ch*16777216;
            float v000 = __ldg(g + o00 + x0), v001 = __ldg(g + o00 + x1);
            float v010 = __ldg(g + o01 + x0), v011 = __ldg(g + o01 + x1);
            float v100 = __ldg(g + o10 + x0), v101 = __ldg(g + o10 + x1);
            float v110 = __ldg(g + o11 + x0), v111 = __ldg(g + o11 + x1);
            float c00 = v000*(1.0f-wx) + v001*wx;
            float c01 = v010*(1.0f-wx) + v011*wx;
            float c10 = v100*(1.0f-wx) + v101*wx;
            float c11 = v110*(1.0f-wx) + v111*wx;
            float c0  = c00*(1.0f-wy) + c01*wy;
            float c1  = c10*(1.0f-wy) + c11*wy;
            gi[ch] = c0*(1.0f-wz) + c1*wz;
        }
    }
    {
        float fx = fminf(fmaxf((gi[0] + 1.0f)*7.5f, 0.0f), 15.0f);
        float fy = fminf(fmaxf((gi[1] + 1.0f)*7.5f, 0.0f), 15.0f);
        float fz = fminf(fmaxf((gi[2] + 1.0f)*7.5f, 0.0f), 15.0f);
        int x0 = (int)floorf(fx), y0 = (int)floorf(fy), z0 = (int)floorf(fz);
        int x1 = min(x0+1, 15), y1 = min(y0+1, 15), z1 = min(z0+1, 15);
        float wx = fx - (float)x0, wy = fy - (float)y0, wz = fz - (float)z0;
        float mx = 1.0f - wx, my = 1.0f - wy, mz = 1.0f - wz;
        float w000 = mx*my*mz, w001 = wx*my*mz;
        float w010 = mx*wy*mz, w011 = wx*wy*mz;
        float w100 = mx*my*wz, w101 = wx*my*wz;
        float w110 = mx*wy*wz, w111 = wx*wy*wz;
        const float4* fb = (const float4*)g_Ft;
        int b000 = (z0*256 + y0*16 + x0)*8;
        int b001 = (z0*256 + y0*16 + x1)*8;
        int b010 = (z0*256 + y1*16 + x0)*8;
        int b011 = (z0*256 + y1*16 + x1)*8;
        int b100 = (z1*256 + y0*16 + x0)*8;
        int b101 = (z1*256 + y0*16 + x1)*8;
        int b110 = (z1*256 + y1*16 + x0)*8;
        int b111 = (z1*256 + y1*16 + x1)*8;
        #pragma unroll
        for (int q = 0; q < 8; q++) {
            float4 v = __ldg(fb + b000 + q);
            float ax = v.x*w000, ay = v.y*w000, az = v.z*w000, aw = v.w*w000;
            v = __ldg(fb + b001 + q);
            ax = fmaf(v.x, w001, ax); ay = fmaf(v.y, w001, ay);
            az = fmaf(v.z, w001, az); aw = fmaf(v.w, w001, aw);
            v = __ldg(fb + b010 + q);
            ax = fmaf(v.x, w010, ax); ay = fmaf(v.y, w010, ay);
            az = fmaf(v.z, w010, az); aw = fmaf(v.w, w010, aw);
            v = __ldg(fb + b011 + q);
            ax = fmaf(v.x, w011, ax); ay = fmaf(v.y, w011, ay);
            az = fmaf(v.z, w011, az); aw = fmaf(v.w, w011, aw);
            v = __ldg(fb + b100 + q);
            ax = fmaf(v.x, w100, ax); ay = fmaf(v.y, w100, ay);
            az = fmaf(v.z, w100, az); aw = fmaf(v.w, w100, aw);
            v = __ldg(fb + b101 + q);
            ax = fmaf(v.x, w101, ax); ay = fmaf(v.y, w101, ay);
            az = fmaf(v.z, w101, az); aw = fmaf(v.w, w101, aw);
            v = __ldg(fb + b110 + q);
            ax = fmaf(v.x, w110, ax); ay = fmaf(v.y, w110, ay);
            az = fmaf(v.z, w110, az); aw = fmaf(v.w, w110, aw);
            v = __ldg(fb + b111 + q);
            ax = fmaf(v.x, w111, ax); ay = fmaf(v.y, w111, ay);
            az = fmaf(v.z, w111, az); aw = fmaf(v.w, w111, aw);
            x[4*q+0] = ax; x[4*q+1] = ay; x[4*q+2] = az; x[4*q+3] = aw;
        }
    }
}

// ---------------- main fused kernel: 1 block = 1 ray, 256 threads ----------------
#define XP 20   // u32 pitch of X rows (conflict-free fragment loads)

__global__ __launch_bounds__(256, 2)
void nerf_mma(const float* __restrict__ rays_o,
              const float* __restrict__ rays_d,
              const float* __restrict__ G1,
              float* __restrict__ outp)
{
    __shared__ u32   Xs[128*XP];     // X features, bf16x2 per u32, 16 u32/row
    __shared__ float shE[16];        // SH encoding (per-ray uniform)
    __shared__ float sigs[128];      // raw sigma per sample
    __shared__ float rgbs[128][4];   // sigmoid(col) per sample

    const int ray = blockIdx.x;
    const int tid = threadIdx.x;

    const float ox = rays_o[ray*3+0], oy = rays_o[ray*3+1], oz = rays_o[ray*3+2];
    float dx = rays_d[ray*3+0], dy = rays_d[ray*3+1], dz = rays_d[ray*3+2];
    const float dn = sqrtf(dx*dx + dy*dy + dz*dz);
    dx /= dn; dy /= dn; dz /= dn;

    const float b  = ox*dx + oy*dy + oz*dz;
    const float cc = ox*ox + oy*oy + oz*oz - RADIUS_F*RADIUS_F;
    const float disc = b*b - cc;
    const bool hit = disc > 0.0f;
    const float sq = sqrtf(hit ? disc : 1.0f);
    const float tmin = hit ? fmaxf(-b - sq, 0.0f) : 0.0f;
    const float tmax = hit ? (-b + sq) : 0.0f;

    // ---- SH encoding to shared (per-ray uniform; thread 0 writes)
    if (tid == 0) {
        const float x = dx, y = dy, z = dz;
        const float xx = x*x, yy = y*y, zz = z*z;
        const float xy = x*y, yz = y*z, xz = x*z;
        shE[0]  = 0.28209479177387814f;
        shE[1]  = -0.48860251190291987f*y;
        shE[2]  =  0.48860251190291987f*z;
        shE[3]  = -0.48860251190291987f*x;
        shE[4]  =  1.0925484305920792f*xy;
        shE[5]  = -1.0925484305920792f*yz;
        shE[6]  =  0.94617469575756f*zz - 0.31539156525252f;
        shE[7]  = -1.0925484305920792f*xz;
        shE[8]  =  0.5462742152960396f*(xx - yy);
        shE[9]  =  0.5900435899266435f*y*(-3.0f*xx + yy);
        shE[10] =  2.890611442640554f*xy*z;
        shE[11] =  0.4570457994644657f*y*(1.0f - 5.0f*zz);
        shE[12] =  0.3731763325901154f*z*(5.0f*zz - 3.0f);
        shE[13] =  0.4570457994644657f*x*(1.0f - 5.0f*zz);
        shE[14] =  1.445305721320277f*z*(xx - yy);
        shE[15] =  0.5900435899266435f*x*(-xx + 3.0f*yy);
    }

    // ---- sampling phase: threads 0..127, one sample each
    if (tid < 128) {
        const int s = tid;
        const float tmid = tmin + ((float)s + 0.5f) * STEPSZ;
        const bool m = hit && (tmid <= tmax);
        u32* xrow = Xs + s*XP;
        if (m) {
            float xf[32];
            sample_feats(G1, (ox + dx*tmid)/RADIUS_F, (oy + dy*tmid)/RADIUS_F,
                         (oz + dz*tmid)/RADIUS_F, xf);
            #pragma unroll
            for (int i = 0; i < 16; i++) xrow[i] = packbf(xf[2*i], xf[2*i+1]);
        } else {
            #pragma unroll
            for (int i = 0; i < 16; i++) xrow[i] = 0u;
        }
    }
    __syncthreads();

    // ---- MLP phase: all 8 warps; warp w owns samples 16w..16w+15
    {
        const int wid = tid >> 5, lane = tid & 31;
        const int r = lane >> 2, c = lane & 3;
        const int s0 = wid*16 + r, s1 = s0 + 8;
        u32 bfr[2];

        // A fragments of X (K=32 -> 2 k-tiles)
        u32 aX[2][4];
        #pragma unroll
        for (int kt = 0; kt < 2; kt++) {
            aX[kt][0] = Xs[s0*XP + kt*8 + c];
            aX[kt][1] = Xs[s1*XP + kt*8 + c];
            aX[kt][2] = Xs[s0*XP + kt*8 + c + 4];
            aX[kt][3] = Xs[s1*XP + kt*8 + c + 4];
        }

        // ---- L0: X(128x32) @ W0 -> 128x128
        float acc[16][4];
        #pragma unroll
        for (int nt = 0; nt < 16; nt++) {
            acc[nt][0] = acc[nt][1] = acc[nt][2] = acc[nt][3] = 0.0f;
            #pragma unroll
            for (int kt = 0; kt < 2; kt++) {
                ldb(bfr, PB_L0, nt, kt, 2, lane);
                mma_bf16(acc[nt], aX[kt], bfr);
            }
        }
        // relu -> A fragments (8 k-tiles)
        u32 ah[8][4];
        #pragma unroll
        for (int kt = 0; kt < 8; kt++) {
            ah[kt][0] = packbf_relu(acc[2*kt][0],   acc[2*kt][1]);
            ah[kt][1] = packbf_relu(acc[2*kt][2],   acc[2*kt][3]);
            ah[kt][2] = packbf_relu(acc[2*kt+1][0], acc[2*kt+1][1]);
            ah[kt][3] = packbf_relu(acc[2*kt+1][2], acc[2*kt+1][3]);
        }

        // ---- L1: H1 @ W1 -> 128x128
        #pragma unroll
        for (int nt = 0; nt < 16; nt++) {
            acc[nt][0] = acc[nt][1] = acc[nt][2] = acc[nt][3] = 0.0f;
            #pragma unroll
            for (int kt = 0; kt < 8; kt++) {
                ldb(bfr, PB_L1, nt, kt, 8, lane);
                mma_bf16(acc[nt], ah[kt], bfr);
            }
        }
        #pragma unroll
        for (int kt = 0; kt < 8; kt++) {
            ah[kt][0] = packbf_relu(acc[2*kt][0],   acc[2*kt][1]);
            ah[kt][1] = packbf_relu(acc[2*kt][2],   acc[2*kt][3]);
            ah[kt][2] = packbf_relu(acc[2*kt+1][0], acc[2*kt+1][1]);
            ah[kt][3] = packbf_relu(acc[2*kt+1][2], acc[2*kt+1][3]);
        }

        // ---- L2: H2 @ W2' -> 128x16  (cols rotated; col15 = sigma)
        float dsig[2][4];
        #pragma unroll
        for (int nt = 0; nt < 2; nt++) {
            dsig[nt][0] = dsig[nt][1] = dsig[nt][2] = dsig[nt][3] = 0.0f;
            #pragma unroll
            for (int kt = 0; kt < 8; kt++) {
                ldb(bfr, PB_L2, nt, kt, 8, lane);
                mma_bf16(dsig[nt], ah[kt], bfr);
            }
        }
        // sigma (raw) lives at col 15 -> lanes with c==3, regs c1/c3 of n-tile 1
        if (c == 3) {
            sigs[s0] = dsig[1][1];
            sigs[s1] = dsig[1][3];
        }

        // ---- color input fragments: k-tile0 = enc (uniform rows), k-tile1 = dsig raw
        u32 ae0[4], ae1[4];
        {
            u32 lo = packbf(shE[2*c],     shE[2*c+1]);
            u32 hi = packbf(shE[8 + 2*c], shE[9 + 2*c]);
            ae0[0] = lo; ae0[1] = lo; ae0[2] = hi; ae0[3] = hi;
        }
        ae1[0] = packbf(dsig[0][0], dsig[0][1]);
        ae1[1] = packbf(dsig[0][2], dsig[0][3]);
        ae1[2] = packbf(dsig[1][0], dsig[1][1]);
        ae1[3] = packbf(dsig[1][2], dsig[1][3]);

        // ---- C0: Cin(128x32) @ Wc0 -> 128x64
        float dc[8][4];
        #pragma unroll
        for (int nt = 0; nt < 8; nt++) {
            dc[nt][0] = dc[nt][1] = dc[nt][2] = dc[nt][3] = 0.0f;
            ldb(bfr, PB_C0, nt, 0, 2, lane); mma_bf16(dc[nt], ae0, bfr);
            ldb(bfr, PB_C0, nt, 1, 2, lane); mma_bf16(dc[nt], ae1, bfr);
        }
        u32 ag[4][4];
        #pragma unroll
        for (int kt = 0; kt < 4; kt++) {
            ag[kt][0] = packbf_relu(dc[2*kt][0],   dc[2*kt][1]);
            ag[kt][1] = packbf_relu(dc[2*kt][2],   dc[2*kt][3]);
            ag[kt][2] = packbf_relu(dc[2*kt+1][0], dc[2*kt+1][1]);
            ag[kt][3] = packbf_relu(dc[2*kt+1][2], dc[2*kt+1][3]);
        }

        // ---- C1: G1h @ Wc1 -> 128x64
        #pragma unroll
        for (int nt = 0; nt < 8; nt++) {
            dc[nt][0] = dc[nt][1] = dc[nt][2] = dc[nt][3] = 0.0f;
            #pragma unroll
            for (int kt = 0; kt < 4; kt++) {
                ldb(bfr, PB_C1, nt, kt, 4, lane);
                mma_bf16(dc[nt], ag[kt], bfr);
            }
        }
        #pragma unroll
        for (int kt = 0; kt < 4; kt++) {
            ag[kt][0] = packbf_relu(dc[2*kt][0],   dc[2*kt][1]);
            ag[kt][1] = packbf_relu(dc[2*kt][2],   dc[2*kt][3]);
            ag[kt][2] = packbf_relu(dc[2*kt+1][0], dc[2*kt+1][1]);
            ag[kt][3] = packbf_relu(dc[2*kt+1][2], dc[2*kt+1][3]);
        }

        // ---- C2: G2h @ Wc2 -> 128x8 (cols 0,1,2 = r,g,b)
        float drgb[4] = {0.0f, 0.0f, 0.0f, 0.0f};
        #pragma unroll
        for (int kt = 0; kt < 4; kt++) {
            ldb(bfr, PB_C2, 0, kt, 4, lane);
            mma_bf16(drgb, ag[kt], bfr);
        }
        if (c == 0) {   // cols 0,1 -> R,G
            rgbs[s0][0] = sigm(drgb[0]); rgbs[s0][1] = sigm(drgb[1]);
            rgbs[s1][0] = sigm(drgb[2]); rgbs[s1][1] = sigm(drgb[3]);
        }
        if (c == 1) {   // col 2 -> B
            rgbs[s0][2] = sigm(drgb[0]);
            rgbs[s1][2] = sigm(drgb[2]);
        }
    }
    __syncthreads();

    // ---- compositing (serial, thread 0)
    if (tid == 0) {
        float T = 1.0f, wsum = 0.0f;
        float rr = 0.0f, gg = 0.0f, bb = 0.0f;
        #pragma unroll 4
        for (int i = 0; i < 128; i++) {
            const float sg = fmaxf(sigs[i], 0.0f);
            const float a  = 1.0f - expf(-sg * STEPSZ);
            const float w  = a * T;
            rr   = fmaf(w, rgbs[i][0], rr);
            gg   = fmaf(w, rgbs[i][1], gg);
            bb   = fmaf(w, rgbs[i][2], bb);
            wsum += w;
            T *= (1.0f - a + 1e-10f);
        }
        const float bg = 1.0f - wsum;
        outp[ray*3+0] = rr + bg;
        outp[ray*3+1] = gg + bg;
        outp[ray*3+2] = bb + bg;
    }
}

// ---------------- launch ----------------
extern "C" void kernel_launch(void* const* d_in, const int* in_sizes, int n_in,
                              void* d_out, int out_size)
{
    const float* rays_o = (const float*)d_in[0];
    const float* rays_d = (const float*)d_in[1];
    const float* G1     = (const float*)d_in[2];
    const float* F      = (const float*)d_in[3];
    const float* W0     = (const float*)d_in[4];
    const float* W1     = (const float*)d_in[5];
    const float* W2     = (const float*)d_in[6];
    const float* Wc0    = (const float*)d_in[7];
    const float* Wc1    = (const float*)d_in[8];
    const float* Wc2    = (const float*)d_in[9];
    float* outp = (float*)d_out;

    const int B = in_sizes[0] / 3;

    transpose_F_kernel<<<512, 256>>>(F);
    //                      W     base   KT NT Korig Norig stride reorder
    pack_kernel<<<16, 128>>>(W0,  PB_L0, 2, 16, 32,  128, 128, 0);
    pack_kernel<<<64, 128>>>(W1,  PB_L1, 8, 16, 128, 128, 128, 0);
    pack_kernel<<< 8, 128>>>(W2,  PB_L2, 8, 2,  128, 16,  16,  1);
    pack_kernel<<< 8, 128>>>(Wc0, PB_C0, 2, 8,  31,  64,  64,  0);
    pack_kernel<<<16, 128>>>(Wc1, PB_C1, 4, 8,  64,  64,  64,  0);
    pack_kernel<<< 2, 128>>>(Wc2, PB_C2, 4, 1,  64,  3,   3,   0);

    nerf_mma<<<B, 256>>>(rays_o, rays_d, G1, outp);
}

// round 10
// speedup vs baseline: 10.5928x; 1.3649x over previous
#include <cuda_runtime.h>
#include <cuda_bf16.h>
#include <math.h>

typedef unsigned int u32;

#define RADIUS_F 1.3f
#define STEPSZ   0.02f

// ---------------- global scratch (no allocs allowed) ----------------
__device__ float g_Ft[131072];      // F transposed (idx, 32ch)
__device__ u32   g_pack[14592];     // all weights in bf16 B-fragment order

// pack-buffer bases (u32 units)
#define PB_L0 0        // W0  K=32  N=128  KT=2 NT=16 -> 2048
#define PB_L1 2048     // W1  K=128 N=128  KT=8 NT=16 -> 8192
#define PB_L2 10240    // W2  K=128 N=16   KT=8 NT=2  -> 1024 (cols rotated; col15 = sigma)
#define PB_C0 11264    // Wc0 K=32(31+pad) N=64 KT=2 NT=8 -> 1024
#define PB_C1 12288    // Wc1 K=64  N=64   KT=4 NT=8 -> 2048
#define PB_C2 14336    // Wc2 K=64  N=8(3+pad) KT=4 NT=1 -> 256

// ---------------- single merged prep kernel ----------------
__device__ __forceinline__ void pack_one(const float* __restrict__ W, int base, int j,
                                         int KT, int Korig, int Norig, int rowstride,
                                         int sig_reorder)
{
    int r    = j & 1;
    int lane = (j >> 1) & 31;
    int t    = j >> 6;           // = nt*KT + kt
    int kt   = t % KT;
    int nt   = t / KT;
    int k = kt*16 + (lane & 3)*2 + r*8;
    int n = nt*8 + (lane >> 2);
    int nc = sig_reorder ? ((n == 15) ? 0 : n + 1) : n;
    float w0 = (k     < Korig && nc < Norig) ? W[k*rowstride + nc]     : 0.0f;
    float w1 = (k + 1 < Korig && nc < Norig) ? W[(k+1)*rowstride + nc] : 0.0f;
    __nv_bfloat162 p = __floats2bfloat162_rn(w0, w1);
    g_pack[base + j] = *(u32*)&p;
}

__global__ void prep_kernel(const float* __restrict__ F,
                            const float* __restrict__ W0,
                            const float* __restrict__ W1,
                            const float* __restrict__ W2,
                            const float* __restrict__ Wc0,
                            const float* __restrict__ Wc1,
                            const float* __restrict__ Wc2)
{
    int idx = blockIdx.x * blockDim.x + threadIdx.x;
    if (idx < 131072) {
        int ch  = idx >> 12;
        int e   = idx & 4095;
        g_Ft[e * 32 + ch] = F[idx];
        return;
    }
    int j = idx - 131072;
    if (j < 2048)       pack_one(W0,  PB_L0, j,         2, 32,  128, 128, 0);
    else if (j < 10240) pack_one(W1,  PB_L1, j - 2048,  8, 128, 128, 128, 0);
    else if (j < 11264) pack_one(W2,  PB_L2, j - 10240, 8, 128, 16,  16,  1);
    else if (j < 12288) pack_one(Wc0, PB_C0, j - 11264, 2, 31,  64,  64,  0);
    else if (j < 14336) pack_one(Wc1, PB_C1, j - 12288, 4, 64,  64,  64,  0);
    else if (j < 14592) pack_one(Wc2, PB_C2, j - 14336, 4, 64,  3,   3,   0);
}

// ---------------- device helpers ----------------
__device__ __forceinline__ u32 packbf(float lo, float hi) {
    __nv_bfloat162 p = __floats2bfloat162_rn(lo, hi);
    return *(u32*)&p;
}
__device__ __forceinline__ u32 packbf_relu(float lo, float hi) {
    return packbf(fmaxf(lo, 0.0f), fmaxf(hi, 0.0f));
}
__device__ __forceinline__ void mma_bf16(float* d, const u32* a, const u32* b) {
    asm volatile(
        "mma.sync.aligned.m16n8k16.row.col.f32.bf16.bf16.f32 "
        "{%0,%1,%2,%3},{%4,%5,%6,%7},{%8,%9},{%0,%1,%2,%3};"
        : "+f"(d[0]), "+f"(d[1]), "+f"(d[2]), "+f"(d[3])
        : "r"(a[0]), "r"(a[1]), "r"(a[2]), "r"(a[3]), "r"(b[0]), "r"(b[1]));
}
__device__ __forceinline__ void ldb(u32* b, int base, int nt, int kt, int KT, int lane) {
    const uint2* p = (const uint2*)(g_pack + base + (((nt*KT + kt) << 5) + lane)*2);
    uint2 v = __ldg(p);
    b[0] = v.x; b[1] = v.y;
}
__device__ __forceinline__ float sigm(float v) { return 1.0f / (1.0f + expf(-v)); }

// G1 trilinear (3ch, 256^3) then F trilinear (32ch via g_Ft) -> x[32]
__device__ __forceinline__ void sample_feats(const float* __restrict__ G1,
                                             float px, float py, float pz,
                                             float* __restrict__ x)
{
    float gi[3];
    {
        float fx = fminf(fmaxf((px + 1.0f)*0.5f*255.0f, 0.0f), 255.0f);
        float fy = fminf(fmaxf((py + 1.0f)*0.5f*255.0f, 0.0f), 255.0f);
        float fz = fminf(fmaxf((pz + 1.0f)*0.5f*255.0f, 0.0f), 255.0f);
        int x0 = (int)floorf(fx), y0 = (int)floorf(fy), z0 = (int)floorf(fz);
        int x1 = min(x0+1, 255), y1 = min(y0+1, 255), z1 = min(z0+1, 255);
        float wx = fx - (float)x0, wy = fy - (float)y0, wz = fz - (float)z0;
        int o00 = z0*65536 + y0*256;
        int o01 = z0*65536 + y1*256;
        int o10 = z1*65536 + y0*256;
        int o11 = z1*65536 + y1*256;
        #pragma unroll
        for (int ch = 0; ch < 3; ch++) {
            const float* g = G1 + ch*16777216;
            float v000 = __ldg(g + o00 + x0), v001 = __ldg(g + o00 + x1);
            float v010 = __ldg(g + o01 + x0), v011 = __ldg(g + o01 + x1);
            float v100 = __ldg(g + o10 + x0), v101 = __ldg(g + o10 + x1);
            float v110 = __ldg(g + o11 + x0), v111 = __ldg(g + o11 + x1);
            float c00 = v000*(1.0f-wx) + v001*wx;
            float c01 = v010*(1.0f-wx) + v011*wx;
            float c10 = v100*(1.0f-wx) + v101*wx;
            float c11 = v110*(1.0f-wx) + v111*wx;
            float c0  = c00*(1.0f-wy) + c01*wy;
            float c1  = c10*(1.0f-wy) + c11*wy;
            gi[ch] = c0*(1.0f-wz) + c1*wz;
        }
    }
    {
        float fx = fminf(fmaxf((gi[0] + 1.0f)*7.5f, 0.0f), 15.0f);
        float fy = fminf(fmaxf((gi[1] + 1.0f)*7.5f, 0.0f), 15.0f);
        float fz = fminf(fmaxf((gi[2] + 1.0f)*7.5f, 0.0f), 15.0f);
        int x0 = (int)floorf(fx), y0 = (int)floorf(fy), z0 = (int)floorf(fz);
        int x1 = min(x0+1, 15), y1 = min(y0+1, 15), z1 = min(z0+1, 15);
        float wx = fx - (float)x0, wy = fy - (float)y0, wz = fz - (float)z0;
        float mx = 1.0f - wx, my = 1.0f - wy, mz = 1.0f - wz;
        float w000 = mx*my*mz, w001 = wx*my*mz;
        float w010 = mx*wy*mz, w011 = wx*wy*mz;
        float w100 = mx*my*wz, w101 = wx*my*wz;
        float w110 = mx*wy*wz, w111 = wx*wy*wz;
        const float4* fb = (const float4*)g_Ft;
        int b000 = (z0*256 + y0*16 + x0)*8;
        int b001 = (z0*256 + y0*16 + x1)*8;
        int b010 = (z0*256 + y1*16 + x0)*8;
        int b011 = (z0*256 + y1*16 + x1)*8;
        int b100 = (z1*256 + y0*16 + x0)*8;
        int b101 = (z1*256 + y0*16 + x1)*8;
        int b110 = (z1*256 + y1*16 + x0)*8;
        int b111 = (z1*256 + y1*16 + x1)*8;
        #pragma unroll
        for (int q = 0; q < 8; q++) {
            float4 v = __ldg(fb + b000 + q);
            float ax = v.x*w000, ay = v.y*w000, az = v.z*w000, aw = v.w*w000;
            v = __ldg(fb + b001 + q);
            ax = fmaf(v.x, w001, ax); ay = fmaf(v.y, w001, ay);
            az = fmaf(v.z, w001, az); aw = fmaf(v.w, w001, aw);
            v = __ldg(fb + b010 + q);
            ax = fmaf(v.x, w010, ax); ay = fmaf(v.y, w010, ay);
            az = fmaf(v.z, w010, az); aw = fmaf(v.w, w010, aw);
            v = __ldg(fb + b011 + q);
            ax = fmaf(v.x, w011, ax); ay = fmaf(v.y, w011, ay);
            az = fmaf(v.z, w011, az); aw = fmaf(v.w, w011, aw);
            v = __ldg(fb + b100 + q);
            ax = fmaf(v.x, w100, ax); ay = fmaf(v.y, w100, ay);
            az = fmaf(v.z, w100, az); aw = fmaf(v.w, w100, aw);
            v = __ldg(fb + b101 + q);
            ax = fmaf(v.x, w101, ax); ay = fmaf(v.y, w101, ay);
            az = fmaf(v.z, w101, az); aw = fmaf(v.w, w101, aw);
            v = __ldg(fb + b110 + q);
            ax = fmaf(v.x, w110, ax); ay = fmaf(v.y, w110, ay);
            az = fmaf(v.z, w110, az); aw = fmaf(v.w, w110, aw);
            v = __ldg(fb + b111 + q);
            ax = fmaf(v.x, w111, ax); ay = fmaf(v.y, w111, ay);
            az = fmaf(v.z, w111, az); aw = fmaf(v.w, w111, aw);
            x[4*q+0] = ax; x[4*q+1] = ay; x[4*q+2] = az; x[4*q+3] = aw;
        }
    }
}

// ---------------- main fused kernel: 1 block = 1 ray, 256 threads ----------------
#define XP 20   // u32 pitch of X rows (conflict-free fragment loads)

__global__ __launch_bounds__(256, 2)
void nerf_mma(const float* __restrict__ rays_o,
              const float* __restrict__ rays_d,
              const float* __restrict__ G1,
              float* __restrict__ outp)
{
    __shared__ u32   Xs[128*XP];     // X features, bf16x2 per u32, 16 u32/row
    __shared__ float shE[16];        // SH encoding (per-ray uniform)
    __shared__ float sigs[128];      // raw sigma per sample
    __shared__ float rgbs[128][4];   // sigmoid(col) per sample

    const int ray = blockIdx.x;
    const int tid = threadIdx.x;

    const float ox = rays_o[ray*3+0], oy = rays_o[ray*3+1], oz = rays_o[ray*3+2];
    float dx = rays_d[ray*3+0], dy = rays_d[ray*3+1], dz = rays_d[ray*3+2];
    const float dn = sqrtf(dx*dx + dy*dy + dz*dz);
    dx /= dn; dy /= dn; dz /= dn;

    const float b  = ox*dx + oy*dy + oz*dz;
    const float cc = ox*ox + oy*oy + oz*oz - RADIUS_F*RADIUS_F;
    const float disc = b*b - cc;
    const bool hit = disc > 0.0f;
    const float sq = sqrtf(hit ? disc : 1.0f);
    const float tmin = hit ? fmaxf(-b - sq, 0.0f) : 0.0f;
    const float tmax = hit ? (-b + sq) : 0.0f;

    // ---- SH encoding to shared (per-ray uniform; thread 0 writes)
    if (tid == 0) {
        const float x = dx, y = dy, z = dz;
        const float xx = x*x, yy = y*y, zz = z*z;
        const float xy = x*y, yz = y*z, xz = x*z;
        shE[0]  = 0.28209479177387814f;
        shE[1]  = -0.48860251190291987f*y;
        shE[2]  =  0.48860251190291987f*z;
        shE[3]  = -0.48860251190291987f*x;
        shE[4]  =  1.0925484305920792f*xy;
        shE[5]  = -1.0925484305920792f*yz;
        shE[6]  =  0.94617469575756f*zz - 0.31539156525252f;
        shE[7]  = -1.0925484305920792f*xz;
        shE[8]  =  0.5462742152960396f*(xx - yy);
        shE[9]  =  0.5900435899266435f*y*(-3.0f*xx + yy);
        shE[10] =  2.890611442640554f*xy*z;
        shE[11] =  0.4570457994644657f*y*(1.0f - 5.0f*zz);
        shE[12] =  0.3731763325901154f*z*(5.0f*zz - 3.0f);
        shE[13] =  0.4570457994644657f*x*(1.0f - 5.0f*zz);
        shE[14] =  1.445305721320277f*z*(xx - yy);
        shE[15] =  0.5900435899266435f*x*(-xx + 3.0f*yy);
    }

    // ---- sampling phase: threads 0..127, one sample each
    if (tid < 128) {
        const int s = tid;
        const float tmid = tmin + ((float)s + 0.5f) * STEPSZ;
        const bool m = hit && (tmid <= tmax);
        u32* xrow = Xs + s*XP;
        if (m) {
            float xf[32];
            sample_feats(G1, (ox + dx*tmid)/RADIUS_F, (oy + dy*tmid)/RADIUS_F,
                         (oz + dz*tmid)/RADIUS_F, xf);
            #pragma unroll
            for (int i = 0; i < 16; i++) xrow[i] = packbf(xf[2*i], xf[2*i+1]);
        } else {
            // clean state for (possibly skipped) masked samples
            #pragma unroll
            for (int i = 0; i < 16; i++) xrow[i] = 0u;
            sigs[s] = 0.0f;
            rgbs[s][0] = 0.0f; rgbs[s][1] = 0.0f; rgbs[s][2] = 0.0f;
        }
    }
    __syncthreads();

    // ---- MLP phase: warp w owns samples 16w..16w+15.
    // mask is monotone decreasing in s -> if a warp's first sample is masked,
    // all 16 are masked; MLP has no bias so MLP(0)=0 => sigma=0 => skip safely.
    {
        const int wid = tid >> 5, lane = tid & 31;
        const bool warp_active =
            hit && (tmin + ((float)(wid*16) + 0.5f)*STEPSZ <= tmax);
        if (warp_active) {
        const int r = lane >> 2, c = lane & 3;
        const int s0 = wid*16 + r, s1 = s0 + 8;
        u32 bfr[2];

        // A fragments of X (K=32 -> 2 k-tiles)
        u32 aX[2][4];
        #pragma unroll
        for (int kt = 0; kt < 2; kt++) {
            aX[kt][0] = Xs[s0*XP + kt*8 + c];
            aX[kt][1] = Xs[s1*XP + kt*8 + c];
            aX[kt][2] = Xs[s0*XP + kt*8 + c + 4];
            aX[kt][3] = Xs[s1*XP + kt*8 + c + 4];
        }

        // ---- L0: X(128x32) @ W0 -> 128x128
        float acc[16][4];
        #pragma unroll
        for (int nt = 0; nt < 16; nt++) {
            acc[nt][0] = acc[nt][1] = acc[nt][2] = acc[nt][3] = 0.0f;
            #pragma unroll
            for (int kt = 0; kt < 2; kt++) {
                ldb(bfr, PB_L0, nt, kt, 2, lane);
                mma_bf16(acc[nt], aX[kt], bfr);
            }
        }
        u32 ah[8][4];
        #pragma unroll
        for (int kt = 0; kt < 8; kt++) {
            ah[kt][0] = packbf_relu(acc[2*kt][0],   acc[2*kt][1]);
            ah[kt][1] = packbf_relu(acc[2*kt][2],   acc[2*kt][3]);
            ah[kt][2] = packbf_relu(acc[2*kt+1][0], acc[2*kt+1][1]);
            ah[kt][3] = packbf_relu(acc[2*kt+1][2], acc[2*kt+1][3]);
        }

        // ---- L1: H1 @ W1 -> 128x128
        #pragma unroll
        for (int nt = 0; nt < 16; nt++) {
            acc[nt][0] = acc[nt][1] = acc[nt][2] = acc[nt][3] = 0.0f;
            #pragma unroll
            for (int kt = 0; kt < 8; kt++) {
                ldb(bfr, PB_L1, nt, kt, 8, lane);
                mma_bf16(acc[nt], ah[kt], bfr);
            }
        }
        #pragma unroll
        for (int kt = 0; kt < 8; kt++) {
            ah[kt][0] = packbf_relu(acc[2*kt][0],   acc[2*kt][1]);
            ah[kt][1] = packbf_relu(acc[2*kt][2],   acc[2*kt][3]);
            ah[kt][2] = packbf_relu(acc[2*kt+1][0], acc[2*kt+1][1]);
            ah[kt][3] = packbf_relu(acc[2*kt+1][2], acc[2*kt+1][3]);
        }

        // ---- L2: H2 @ W2' -> 128x16  (cols rotated; col15 = sigma)
        float dsig[2][4];
        #pragma unroll
        for (int nt = 0; nt < 2; nt++) {
            dsig[nt][0] = dsig[nt][1] = dsig[nt][2] = dsig[nt][3] = 0.0f;
            #pragma unroll
            for (int kt = 0; kt < 8; kt++) {
                ldb(bfr, PB_L2, nt, kt, 8, lane);
                mma_bf16(dsig[nt], ah[kt], bfr);
            }
        }
        if (c == 3) {
            sigs[s0] = dsig[1][1];
            sigs[s1] = dsig[1][3];
        }

        // ---- color input fragments: k-tile0 = enc (uniform rows), k-tile1 = dsig raw
        u32 ae0[4], ae1[4];
        {
            u32 lo = packbf(shE[2*c],     shE[2*c+1]);
            u32 hi = packbf(shE[8 + 2*c], shE[9 + 2*c]);
            ae0[0] = lo; ae0[1] = lo; ae0[2] = hi; ae0[3] = hi;
        }
        ae1[0] = packbf(dsig[0][0], dsig[0][1]);
        ae1[1] = packbf(dsig[0][2], dsig[0][3]);
        ae1[2] = packbf(dsig[1][0], dsig[1][1]);
        ae1[3] = packbf(dsig[1][2], dsig[1][3]);

        // ---- C0: Cin(128x32) @ Wc0 -> 128x64
        float dc[8][4];
        #pragma unroll
        for (int nt = 0; nt < 8; nt++) {
            dc[nt][0] = dc[nt][1] = dc[nt][2] = dc[nt][3] = 0.0f;
            ldb(bfr, PB_C0, nt, 0, 2, lane); mma_bf16(dc[nt], ae0, bfr);
            ldb(bfr, PB_C0, nt, 1, 2, lane); mma_bf16(dc[nt], ae1, bfr);
        }
        u32 ag[4][4];
        #pragma unroll
        for (int kt = 0; kt < 4; kt++) {
            ag[kt][0] = packbf_relu(dc[2*kt][0],   dc[2*kt][1]);
            ag[kt][1] = packbf_relu(dc[2*kt][2],   dc[2*kt][3]);
            ag[kt][2] = packbf_relu(dc[2*kt+1][0], dc[2*kt+1][1]);
            ag[kt][3] = packbf_relu(dc[2*kt+1][2], dc[2*kt+1][3]);
        }

        // ---- C1: G1h @ Wc1 -> 128x64
        #pragma unroll
        for (int nt = 0; nt < 8; nt++) {
            dc[nt][0] = dc[nt][1] = dc[nt][2] = dc[nt][3] = 0.0f;
            #pragma unroll
            for (int kt = 0; kt < 4; kt++) {
                ldb(bfr, PB_C1, nt, kt, 4, lane);
                mma_bf16(dc[nt], ag[kt], bfr);
            }
        }
        #pragma unroll
        for (int kt = 0; kt < 4; kt++) {
            ag[kt][0] = packbf_relu(dc[2*kt][0],   dc[2*kt][1]);
            ag[kt][1] = packbf_relu(dc[2*kt][2],   dc[2*kt][3]);
            ag[kt][2] = packbf_relu(dc[2*kt+1][0], dc[2*kt+1][1]);
            ag[kt][3] = packbf_relu(dc[2*kt+1][2], dc[2*kt+1][3]);
        }

        // ---- C2: G2h @ Wc2 -> 128x8 (cols 0,1,2 = r,g,b)
        float drgb[4] = {0.0f, 0.0f, 0.0f, 0.0f};
        #pragma unroll
        for (int kt = 0; kt < 4; kt++) {
            ldb(bfr, PB_C2, 0, kt, 4, lane);
            mma_bf16(drgb, ag[kt], bfr);
        }
        if (c == 0) {   // cols 0,1 -> R,G
            rgbs[s0][0] = sigm(drgb[0]); rgbs[s0][1] = sigm(drgb[1]);
            rgbs[s1][0] = sigm(drgb[2]); rgbs[s1][1] = sigm(drgb[3]);
        }
        if (c == 1) {   // col 2 -> B
            rgbs[s0][2] = sigm(drgb[0]);
            rgbs[s1][2] = sigm(drgb[2]);
        }
        } // warp_active
    }
    __syncthreads();

    // ---- compositing: warp 0 parallel scan (4 samples per lane, in order)
    if (tid < 32) {
        const int lane = tid;
        float Tl = 1.0f;                   // local running transmittance
        float rr = 0.0f, gg = 0.0f, bb = 0.0f, ws = 0.0f;
        #pragma unroll
        for (int j = 0; j < 4; j++) {
            const int i = lane*4 + j;
            const float sg = fmaxf(sigs[i], 0.0f);
            const float a  = 1.0f - expf(-sg * STEPSZ);
            const float w  = a * Tl;
            rr += w * rgbs[i][0];
            gg += w * rgbs[i][1];
            bb += w * rgbs[i][2];
            ws += w;
            Tl *= (1.0f - a + 1e-10f);
        }
        // inclusive scan of per-lane transmittance product
        float inc = Tl;
        #pragma unroll
        for (int off = 1; off < 32; off <<= 1) {
            float v = __shfl_up_sync(0xFFFFFFFFu, inc, off);
            if (lane >= off) inc *= v;
        }
        // exclusive product for this lane's segment
        float exc = __shfl_up_sync(0xFFFFFFFFu, inc, 1);
        if (lane == 0) exc = 1.0f;
        rr *= exc; gg *= exc; bb *= exc; ws *= exc;
        // reduce
        #pragma unroll
        for (int off = 16; off > 0; off >>= 1) {
            rr += __shfl_down_sync(0xFFFFFFFFu, rr, off);
            gg += __shfl_down_sync(0xFFFFFFFFu, gg, off);
            bb += __shfl_down_sync(0xFFFFFFFFu, bb, off);
            ws += __shfl_down_sync(0xFFFFFFFFu, ws, off);
        }
        if (lane == 0) {
            const float bg = 1.0f - ws;
            outp[ray*3+0] = rr + bg;
            outp[ray*3+1] = gg + bg;
            outp[ray*3+2] = bb + bg;
        }
    }
}

// ---------------- launch ----------------
extern "C" void kernel_launch(void* const* d_in, const int* in_sizes, int n_in,
                              void* d_out, int out_size)
{
    const float* rays_o = (const float*)d_in[0];
    const float* rays_d = (const float*)d_in[1];
    const float* G1     = (const float*)d_in[2];
    const float* F      = (const float*)d_in[3];
    const float* W0     = (const float*)d_in[4];
    const float* W1     = (const float*)d_in[5];
    const float* W2     = (const float*)d_in[6];
    const float* Wc0    = (const float*)d_in[7];
    const float* Wc1    = (const float*)d_in[8];
    const float* Wc2    = (const float*)d_in[9];
    float* outp = (float*)d_out;

    const int B = in_sizes[0] / 3;

    // one merged prep launch: 131072 (transpose F) + 14592 (pack) threads
    prep_kernel<<<(131072 + 14592 + 255)/256, 256>>>(F, W0, W1, W2, Wc0, Wc1, Wc2);

    nerf_mma<<<B, 256>>>(rays_o, rays_d, G1, outp);
}

// round 11
// speedup vs baseline: 13.0124x; 1.2284x over previous
#include <cuda_runtime.h>
#include <cuda_bf16.h>
#include <math.h>

typedef unsigned int u32;

#define RADIUS_F 1.3f
#define STEPSZ   0.02f

// ---------------- global scratch (no allocs allowed) ----------------
__device__ float g_Ft[131072];      // F transposed (idx, 32ch)
__device__ u32   g_pack[14592];     // all weights in bf16 B-fragment order

// pack-buffer bases (u32 units)
#define PB_L0 0        // W0  K=32  N=128  KT=2 NT=16 -> 2048
#define PB_L1 2048     // W1  K=128 N=128  KT=8 NT=16 -> 8192
#define PB_L2 10240    // W2  K=128 N=16   KT=8 NT=2  -> 1024 (cols rotated; col15 = sigma)
#define PB_C0 11264    // Wc0 K=32(31+pad) N=64 KT=2 NT=8 -> 1024
#define PB_C1 12288    // Wc1 K=64  N=64   KT=4 NT=8 -> 2048
#define PB_C2 14336    // Wc2 K=64  N=8(3+pad) KT=4 NT=1 -> 256

// ---------------- single merged prep kernel ----------------
__device__ __forceinline__ void pack_one(const float* __restrict__ W, int base, int j,
                                         int KT, int Korig, int Norig, int rowstride,
                                         int sig_reorder)
{
    int r    = j & 1;
    int lane = (j >> 1) & 31;
    int t    = j >> 6;           // = nt*KT + kt
    int kt   = t % KT;
    int nt   = t / KT;
    int k = kt*16 + (lane & 3)*2 + r*8;
    int n = nt*8 + (lane >> 2);
    int nc = sig_reorder ? ((n == 15) ? 0 : n + 1) : n;
    float w0 = (k     < Korig && nc < Norig) ? W[k*rowstride + nc]     : 0.0f;
    float w1 = (k + 1 < Korig && nc < Norig) ? W[(k+1)*rowstride + nc] : 0.0f;
    __nv_bfloat162 p = __floats2bfloat162_rn(w0, w1);
    g_pack[base + j] = *(u32*)&p;
}

__global__ void prep_kernel(const float* __restrict__ F,
                            const float* __restrict__ W0,
                            const float* __restrict__ W1,
                            const float* __restrict__ W2,
                            const float* __restrict__ Wc0,
                            const float* __restrict__ Wc1,
                            const float* __restrict__ Wc2)
{
    int idx = blockIdx.x * blockDim.x + threadIdx.x;
    if (idx < 131072) {
        int ch  = idx >> 12;
        int e   = idx & 4095;
        g_Ft[e * 32 + ch] = F[idx];
        return;
    }
    int j = idx - 131072;
    if (j < 2048)       pack_one(W0,  PB_L0, j,         2, 32,  128, 128, 0);
    else if (j < 10240) pack_one(W1,  PB_L1, j - 2048,  8, 128, 128, 128, 0);
    else if (j < 11264) pack_one(W2,  PB_L2, j - 10240, 8, 128, 16,  16,  1);
    else if (j < 12288) pack_one(Wc0, PB_C0, j - 11264, 2, 31,  64,  64,  0);
    else if (j < 14336) pack_one(Wc1, PB_C1, j - 12288, 4, 64,  64,  64,  0);
    else if (j < 14592) pack_one(Wc2, PB_C2, j - 14336, 4, 64,  3,   3,   0);
}

// ---------------- device helpers ----------------
__device__ __forceinline__ u32 packbf(float lo, float hi) {
    __nv_bfloat162 p = __floats2bfloat162_rn(lo, hi);
    return *(u32*)&p;
}
__device__ __forceinline__ u32 packbf_relu(float lo, float hi) {
    return packbf(fmaxf(lo, 0.0f), fmaxf(hi, 0.0f));
}
__device__ __forceinline__ void mma_bf16(float* d, const u32* a, const u32* b) {
    asm volatile(
        "mma.sync.aligned.m16n8k16.row.col.f32.bf16.bf16.f32 "
        "{%0,%1,%2,%3},{%4,%5,%6,%7},{%8,%9},{%0,%1,%2,%3};"
        : "+f"(d[0]), "+f"(d[1]), "+f"(d[2]), "+f"(d[3])
        : "r"(a[0]), "r"(a[1]), "r"(a[2]), "r"(a[3]), "r"(b[0]), "r"(b[1]));
}
__device__ __forceinline__ void ldb(u32* b, int base, int nt, int kt, int KT, int lane) {
    const uint2* p = (const uint2*)(g_pack + base + (((nt*KT + kt) << 5) + lane)*2);
    uint2 v = __ldg(p);
    b[0] = v.x; b[1] = v.y;
}
__device__ __forceinline__ float sigm(float v) {
    return __fdividef(1.0f, 1.0f + __expf(-v));
}

// G1 trilinear (3ch, 256^3) then F trilinear (32ch via g_Ft) -> x[32]
__device__ __forceinline__ void sample_feats(const float* __restrict__ G1,
                                             float px, float py, float pz,
                                             float* __restrict__ x)
{
    float gi[3];
    {
        float fx = fminf(fmaxf((px + 1.0f)*0.5f*255.0f, 0.0f), 255.0f);
        float fy = fminf(fmaxf((py + 1.0f)*0.5f*255.0f, 0.0f), 255.0f);
        float fz = fminf(fmaxf((pz + 1.0f)*0.5f*255.0f, 0.0f), 255.0f);
        int x0 = (int)floorf(fx), y0 = (int)floorf(fy), z0 = (int)floorf(fz);
        int x1 = min(x0+1, 255), y1 = min(y0+1, 255), z1 = min(z0+1, 255);
        float wx = fx - (float)x0, wy = fy - (float)y0, wz = fz - (float)z0;
        int o00 = z0*65536 + y0*256;
        int o01 = z0*65536 + y1*256;
        int o10 = z1*65536 + y0*256;
        int o11 = z1*65536 + y1*256;
        #pragma unroll
        for (int ch = 0; ch < 3; ch++) {
            const float* g = G1 + ch*16777216;
            float v000 = __ldg(g + o00 + x0), v001 = __ldg(g + o00 + x1);
            float v010 = __ldg(g + o01 + x0), v011 = __ldg(g + o01 + x1);
            float v100 = __ldg(g + o10 + x0), v101 = __ldg(g + o10 + x1);
            float v110 = __ldg(g + o11 + x0), v111 = __ldg(g + o11 + x1);
            float c00 = v000*(1.0f-wx) + v001*wx;
            float c01 = v010*(1.0f-wx) + v011*wx;
            float c10 = v100*(1.0f-wx) + v101*wx;
            float c11 = v110*(1.0f-wx) + v111*wx;
            float c0  = c00*(1.0f-wy) + c01*wy;
            float c1  = c10*(1.0f-wy) + c11*wy;
            gi[ch] = c0*(1.0f-wz) + c1*wz;
        }
    }
    {
        float fx = fminf(fmaxf((gi[0] + 1.0f)*7.5f, 0.0f), 15.0f);
        float fy = fminf(fmaxf((gi[1] + 1.0f)*7.5f, 0.0f), 15.0f);
        float fz = fminf(fmaxf((gi[2] + 1.0f)*7.5f, 0.0f), 15.0f);
        int x0 = (int)floorf(fx), y0 = (int)floorf(fy), z0 = (int)floorf(fz);
        int x1 = min(x0+1, 15), y1 = min(y0+1, 15), z1 = min(z0+1, 15);
        float wx = fx - (float)x0, wy = fy - (float)y0, wz = fz - (float)z0;
        float mx = 1.0f - wx, my = 1.0f - wy, mz = 1.0f - wz;
        float w000 = mx*my*mz, w001 = wx*my*mz;
        float w010 = mx*wy*mz, w011 = wx*wy*mz;
        float w100 = mx*my*wz, w101 = wx*my*wz;
        float w110 = mx*wy*wz, w111 = wx*wy*wz;
        const float4* fb = (const float4*)g_Ft;
        int b000 = (z0*256 + y0*16 + x0)*8;
        int b001 = (z0*256 + y0*16 + x1)*8;
        int b010 = (z0*256 + y1*16 + x0)*8;
        int b011 = (z0*256 + y1*16 + x1)*8;
        int b100 = (z1*256 + y0*16 + x0)*8;
        int b101 = (z1*256 + y0*16 + x1)*8;
        int b110 = (z1*256 + y1*16 + x0)*8;
        int b111 = (z1*256 + y1*16 + x1)*8;
        #pragma unroll
        for (int q = 0; q < 8; q++) {
            float4 v = __ldg(fb + b000 + q);
            float ax = v.x*w000, ay = v.y*w000, az = v.z*w000, aw = v.w*w000;
            v = __ldg(fb + b001 + q);
            ax = fmaf(v.x, w001, ax); ay = fmaf(v.y, w001, ay);
            az = fmaf(v.z, w001, az); aw = fmaf(v.w, w001, aw);
            v = __ldg(fb + b010 + q);
            ax = fmaf(v.x, w010, ax); ay = fmaf(v.y, w010, ay);
            az = fmaf(v.z, w010, az); aw = fmaf(v.w, w010, aw);
            v = __ldg(fb + b011 + q);
            ax = fmaf(v.x, w011, ax); ay = fmaf(v.y, w011, ay);
            az = fmaf(v.z, w011, az); aw = fmaf(v.w, w011, aw);
            v = __ldg(fb + b100 + q);
            ax = fmaf(v.x, w100, ax); ay = fmaf(v.y, w100, ay);
            az = fmaf(v.z, w100, az); aw = fmaf(v.w, w100, aw);
            v = __ldg(fb + b101 + q);
            ax = fmaf(v.x, w101, ax); ay = fmaf(v.y, w101, ay);
            az = fmaf(v.z, w101, az); aw = fmaf(v.w, w101, aw);
            v = __ldg(fb + b110 + q);
            ax = fmaf(v.x, w110, ax); ay = fmaf(v.y, w110, ay);
            az = fmaf(v.z, w110, az); aw = fmaf(v.w, w110, aw);
            v = __ldg(fb + b111 + q);
            ax = fmaf(v.x, w111, ax); ay = fmaf(v.y, w111, ay);
            az = fmaf(v.z, w111, az); aw = fmaf(v.w, w111, aw);
            x[4*q+0] = ax; x[4*q+1] = ay; x[4*q+2] = az; x[4*q+3] = aw;
        }
    }
}

// ---------------- main fused kernel: 1 block = 2 rays, 256 threads ----------------
#define XP 20   // u32 pitch of X rows (conflict-free fragment loads)

__global__ __launch_bounds__(256, 2)
void nerf_mma2(const float* __restrict__ rays_o,
               const float* __restrict__ rays_d,
               const float* __restrict__ G1,
               float* __restrict__ outp)
{
    __shared__ u32   Xs[256*XP];     // X features (2 rays x 128 samples), row = tid
    __shared__ float shE[2][16];     // SH encoding per ray
    __shared__ float shRay[2][3];    // tmin, tmax, hit
    __shared__ float sigs[256];      // raw sigma per combined sample
    __shared__ float rgbs[256][4];   // sigmoid(col) per combined sample

    const int tid  = threadIdx.x;
    const int half = tid >> 7;                 // which ray of the pair
    const int ray  = blockIdx.x*2 + half;

    const float ox = rays_o[ray*3+0], oy = rays_o[ray*3+1], oz = rays_o[ray*3+2];
    float dx = rays_d[ray*3+0], dy = rays_d[ray*3+1], dz = rays_d[ray*3+2];
    const float dn = sqrtf(dx*dx + dy*dy + dz*dz);
    dx /= dn; dy /= dn; dz /= dn;

    const float b  = ox*dx + oy*dy + oz*dz;
    const float cc = ox*ox + oy*oy + oz*oz - RADIUS_F*RADIUS_F;
    const float disc = b*b - cc;
    const bool hit = disc > 0.0f;
    const float sq = sqrtf(hit ? disc : 1.0f);
    const float tmin = hit ? fmaxf(-b - sq, 0.0f) : 0.0f;
    const float tmax = hit ? (-b + sq) : 0.0f;

    const int s = tid & 127;   // sample index within this ray

    // ---- per-ray uniforms to shared (one thread per ray)
    if (s == 0) {
        shRay[half][0] = tmin;
        shRay[half][1] = tmax;
        shRay[half][2] = hit ? 1.0f : 0.0f;
        const float x = dx, y = dy, z = dz;
        const float xx = x*x, yy = y*y, zz = z*z;
        const float xy = x*y, yz = y*z, xz = x*z;
        float* E = shE[half];
        E[0]  = 0.28209479177387814f;
        E[1]  = -0.48860251190291987f*y;
        E[2]  =  0.48860251190291987f*z;
        E[3]  = -0.48860251190291987f*x;
        E[4]  =  1.0925484305920792f*xy;
        E[5]  = -1.0925484305920792f*yz;
        E[6]  =  0.94617469575756f*zz - 0.31539156525252f;
        E[7]  = -1.0925484305920792f*xz;
        E[8]  =  0.5462742152960396f*(xx - yy);
        E[9]  =  0.5900435899266435f*y*(-3.0f*xx + yy);
        E[10] =  2.890611442640554f*xy*z;
        E[11] =  0.4570457994644657f*y*(1.0f - 5.0f*zz);
        E[12] =  0.3731763325901154f*z*(5.0f*zz - 3.0f);
        E[13] =  0.4570457994644657f*x*(1.0f - 5.0f*zz);
        E[14] =  1.445305721320277f*z*(xx - yy);
        E[15] =  0.5900435899266435f*x*(-xx + 3.0f*yy);
    }

    // ---- sampling phase: ALL 256 threads, one sample each (combined row = tid)
    {
        const float tmid = tmin + ((float)s + 0.5f) * STEPSZ;
        const bool m = hit && (tmid <= tmax);
        u32* xrow = Xs + tid*XP;
        if (m) {
            float xf[32];
            sample_feats(G1, (ox + dx*tmid)/RADIUS_F, (oy + dy*tmid)/RADIUS_F,
                         (oz + dz*tmid)/RADIUS_F, xf);
            #pragma unroll
            for (int i = 0; i < 16; i++) xrow[i] = packbf(xf[2*i], xf[2*i+1]);
        } else {
            // clean state for (possibly skipped) masked samples
            #pragma unroll
            for (int i = 0; i < 16; i++) xrow[i] = 0u;
            sigs[tid] = 0.0f;
            rgbs[tid][0] = 0.0f; rgbs[tid][1] = 0.0f; rgbs[tid][2] = 0.0f;
        }
    }
    __syncthreads();

    // ---- MLP phase: 16 tiles of 16 samples; warp w does tiles w (ray0), w+8 (ray1)
    {
        const int wid = tid >> 5, lane = tid & 31;
        const int r = lane >> 2, c = lane & 3;

        #pragma unroll
        for (int ti = 0; ti < 2; ti++) {
            const int t    = wid + ti*8;       // tile 0..15, combined rows 16t..16t+15
            const int rIdx = t >> 3;           // which ray
            const float tmn = shRay[rIdx][0], tmx = shRay[rIdx][1];
            const bool active = (shRay[rIdx][2] > 0.5f) &&
                (tmn + ((float)((t & 7)*16) + 0.5f)*STEPSZ <= tmx);
            if (!active) continue;

            const int s0 = t*16 + r, s1 = s0 + 8;
            u32 bfr[2];

            // A fragments of X (K=32 -> 2 k-tiles)
            u32 aX[2][4];
            #pragma unroll
            for (int kt = 0; kt < 2; kt++) {
                aX[kt][0] = Xs[s0*XP + kt*8 + c];
                aX[kt][1] = Xs[s1*XP + kt*8 + c];
                aX[kt][2] = Xs[s0*XP + kt*8 + c + 4];
                aX[kt][3] = Xs[s1*XP + kt*8 + c + 4];
            }

            // ---- L0: X(16x32) @ W0 -> 16x128
            float acc[16][4];
            #pragma unroll
            for (int nt = 0; nt < 16; nt++) {
                acc[nt][0] = acc[nt][1] = acc[nt][2] = acc[nt][3] = 0.0f;
                #pragma unroll
                for (int kt = 0; kt < 2; kt++) {
                    ldb(bfr, PB_L0, nt, kt, 2, lane);
                    mma_bf16(acc[nt], aX[kt], bfr);
                }
            }
            u32 ah[8][4];
            #pragma unroll
            for (int kt = 0; kt < 8; kt++) {
                ah[kt][0] = packbf_relu(acc[2*kt][0],   acc[2*kt][1]);
                ah[kt][1] = packbf_relu(acc[2*kt][2],   acc[2*kt][3]);
                ah[kt][2] = packbf_relu(acc[2*kt+1][0], acc[2*kt+1][1]);
                ah[kt][3] = packbf_relu(acc[2*kt+1][2], acc[2*kt+1][3]);
            }

            // ---- L1: H1 @ W1 -> 16x128
            #pragma unroll
            for (int nt = 0; nt < 16; nt++) {
                acc[nt][0] = acc[nt][1] = acc[nt][2] = acc[nt][3] = 0.0f;
                #pragma unroll
                for (int kt = 0; kt < 8; kt++) {
                    ldb(bfr, PB_L1, nt, kt, 8, lane);
                    mma_bf16(acc[nt], ah[kt], bfr);
                }
            }
            #pragma unroll
            for (int kt = 0; kt < 8; kt++) {
                ah[kt][0] = packbf_relu(acc[2*kt][0],   acc[2*kt][1]);
                ah[kt][1] = packbf_relu(acc[2*kt][2],   acc[2*kt][3]);
                ah[kt][2] = packbf_relu(acc[2*kt+1][0], acc[2*kt+1][1]);
                ah[kt][3] = packbf_relu(acc[2*kt+1][2], acc[2*kt+1][3]);
            }

            // ---- L2: H2 @ W2' -> 16x16  (cols rotated; col15 = sigma)
            float dsig[2][4];
            #pragma unroll
            for (int nt = 0; nt < 2; nt++) {
                dsig[nt][0] = dsig[nt][1] = dsig[nt][2] = dsig[nt][3] = 0.0f;
                #pragma unroll
                for (int kt = 0; kt < 8; kt++) {
                    ldb(bfr, PB_L2, nt, kt, 8, lane);
                    mma_bf16(dsig[nt], ah[kt], bfr);
                }
            }
            if (c == 3) {
                sigs[s0] = dsig[1][1];
                sigs[s1] = dsig[1][3];
            }

            // ---- color input fragments: k-tile0 = enc (uniform rows), k-tile1 = dsig raw
            u32 ae0[4], ae1[4];
            {
                const float* E = shE[rIdx];
                u32 lo = packbf(E[2*c],     E[2*c+1]);
                u32 hi = packbf(E[8 + 2*c], E[9 + 2*c]);
                ae0[0] = lo; ae0[1] = lo; ae0[2] = hi; ae0[3] = hi;
            }
            ae1[0] = packbf(dsig[0][0], dsig[0][1]);
            ae1[1] = packbf(dsig[0][2], dsig[0][3]);
            ae1[2] = packbf(dsig[1][0], dsig[1][1]);
            ae1[3] = packbf(dsig[1][2], dsig[1][3]);

            // ---- C0: Cin(16x32) @ Wc0 -> 16x64
            float dc[8][4];
            #pragma unroll
            for (int nt = 0; nt < 8; nt++) {
                dc[nt][0] = dc[nt][1] = dc[nt][2] = dc[nt][3] = 0.0f;
                ldb(bfr, PB_C0, nt, 0, 2, lane); mma_bf16(dc[nt], ae0, bfr);
                ldb(bfr, PB_C0, nt, 1, 2, lane); mma_bf16(dc[nt], ae1, bfr);
            }
            u32 ag[4][4];
            #pragma unroll
            for (int kt = 0; kt < 4; kt++) {
                ag[kt][0] = packbf_relu(dc[2*kt][0],   dc[2*kt][1]);
                ag[kt][1] = packbf_relu(dc[2*kt][2],   dc[2*kt][3]);
                ag[kt][2] = packbf_relu(dc[2*kt+1][0], dc[2*kt+1][1]);
                ag[kt][3] = packbf_relu(dc[2*kt+1][2], dc[2*kt+1][3]);
            }

            // ---- C1: G1h @ Wc1 -> 16x64
            #pragma unroll
            for (int nt = 0; nt < 8; nt++) {
                dc[nt][0] = dc[nt][1] = dc[nt][2] = dc[nt][3] = 0.0f;
                #pragma unroll
                for (int kt = 0; kt < 4; kt++) {
                    ldb(bfr, PB_C1, nt, kt, 4, lane);
                    mma_bf16(dc[nt], ag[kt], bfr);
                }
            }
            #pragma unroll
            for (int kt = 0; kt < 4; kt++) {
                ag[kt][0] = packbf_relu(dc[2*kt][0],   dc[2*kt][1]);
                ag[kt][1] = packbf_relu(dc[2*kt][2],   dc[2*kt][3]);
                ag[kt][2] = packbf_relu(dc[2*kt+1][0], dc[2*kt+1][1]);
                ag[kt][3] = packbf_relu(dc[2*kt+1][2], dc[2*kt+1][3]);
            }

            // ---- C2: G2h @ Wc2 -> 16x8 (cols 0,1,2 = r,g,b)
            float drgb[4] = {0.0f, 0.0f, 0.0f, 0.0f};
            #pragma unroll
            for (int kt = 0; kt < 4; kt++) {
                ldb(bfr, PB_C2, 0, kt, 4, lane);
                mma_bf16(drgb, ag[kt], bfr);
            }
            if (c == 0) {   // cols 0,1 -> R,G
                rgbs[s0][0] = sigm(drgb[0]); rgbs[s0][1] = sigm(drgb[1]);
                rgbs[s1][0] = sigm(drgb[2]); rgbs[s1][1] = sigm(drgb[3]);
            }
            if (c == 1) {   // col 2 -> B
                rgbs[s0][2] = sigm(drgb[0]);
                rgbs[s1][2] = sigm(drgb[2]);
            }
        }
    }
    __syncthreads();

    // ---- compositing: warp 0 -> ray0, warp 1 -> ray1 (parallel scan)
    if (tid < 64) {
        const int rIdx = tid >> 5;
        const int lane = tid & 31;
        const int base = rIdx * 128;
        float Tl = 1.0f;
        float rr = 0.0f, gg = 0.0f, bb = 0.0f, ws = 0.0f;
        #pragma unroll
        for (int j = 0; j < 4; j++) {
            const int i = base + lane*4 + j;
            const float sg = fmaxf(sigs[i], 0.0f);
            const float a  = 1.0f - __expf(-sg * STEPSZ);
            const float w  = a * Tl;
            rr += w * rgbs[i][0];
            gg += w * rgbs[i][1];
            bb += w * rgbs[i][2];
            ws += w;
            Tl *= (1.0f - a + 1e-10f);
        }
        float inc = Tl;
        #pragma unroll
        for (int off = 1; off < 32; off <<= 1) {
            float v = __shfl_up_sync(0xFFFFFFFFu, inc, off);
            if (lane >= off) inc *= v;
        }
        float exc = __shfl_up_sync(0xFFFFFFFFu, inc, 1);
        if (lane == 0) exc = 1.0f;
        rr *= exc; gg *= exc; bb *= exc; ws *= exc;
        #pragma unroll
        for (int off = 16; off > 0; off >>= 1) {
            rr += __shfl_down_sync(0xFFFFFFFFu, rr, off);
            gg += __shfl_down_sync(0xFFFFFFFFu, gg, off);
            bb += __shfl_down_sync(0xFFFFFFFFu, bb, off);
            ws += __shfl_down_sync(0xFFFFFFFFu, ws, off);
        }
        if (lane == 0) {
            const int oray = blockIdx.x*2 + rIdx;
            const float bg = 1.0f - ws;
            outp[oray*3+0] = rr + bg;
            outp[oray*3+1] = gg + bg;
            outp[oray*3+2] = bb + bg;
        }
    }
}

// ---------------- launch ----------------
extern "C" void kernel_launch(void* const* d_in, const int* in_sizes, int n_in,
                              void* d_out, int out_size)
{
    const float* rays_o = (const float*)d_in[0];
    const float* rays_d = (const float*)d_in[1];
    const float* G1     = (const float*)d_in[2];
    const float* F      = (const float*)d_in[3];
    const float* W0     = (const float*)d_in[4];
    const float* W1     = (const float*)d_in[5];
    const float* W2     = (const float*)d_in[6];
    const float* Wc0    = (const float*)d_in[7];
    const float* Wc1    = (const float*)d_in[8];
    const float* Wc2    = (const float*)d_in[9];
    float* outp = (float*)d_out;

    const int B = in_sizes[0] / 3;

    prep_kernel<<<(131072 + 14592 + 255)/256, 256>>>(F, W0, W1, W2, Wc0, Wc1, Wc2);

    nerf_mma2<<<B/2, 256>>>(rays_o, rays_d, G1, outp);
}